// round 4
// baseline (speedup 1.0000x reference)
#include <cuda_runtime.h>
#include <cuda_bf16.h>
#include <math.h>
#include <stdint.h>

#define B_    64
#define S_    512
#define H_    1024
#define HD2   512
#define L_    9
#define NTOK  (B_*S_)
#define EPS_  1e-5f
#define LOG2E_ 1.4426950408889634f
#define LN2_   0.6931471805599453f

// ---------------- device scratch (no allocation allowed) -------------------
__device__ __nv_bfloat16 g_xb[(size_t)NTOK * H_];    // LN-normalized X, bf16
__device__ __nv_bfloat16 g_w1t[(size_t)HD2 * H_];    // W1^T bf16 [N][K]
__device__ __nv_bfloat16 g_hb[(size_t)NTOK * HD2];   // post-GELU h, bf16
__device__ float g_em[(size_t)NTOK * L_];            // emissions fp32
__device__ float g_llh[B_];

// ---------------------------------------------------------------------------
__device__ __forceinline__ float ex2f_(float x){ float y; asm("ex2.approx.ftz.f32 %0,%1;":"=f"(y):"f"(x)); return y; }
__device__ __forceinline__ float lg2f_(float x){ float y; asm("lg2.approx.ftz.f32 %0,%1;":"=f"(y):"f"(x)); return y; }

__device__ __forceinline__ void cp16s(uint32_t dst, const void* src){
    asm volatile("cp.async.cg.shared.global [%0], [%1], 16;" :: "r"(dst), "l"(src));
}
__device__ __forceinline__ void ldsm4(uint32_t* r, uint32_t addr){
    asm volatile("ldmatrix.sync.aligned.m8n8.x4.shared.b16 {%0,%1,%2,%3}, [%4];"
        : "=r"(r[0]), "=r"(r[1]), "=r"(r[2]), "=r"(r[3]) : "r"(addr));
}

// ---------------------------------------------------------------------------
// Kernel 1: LayerNorm -> normalized bf16 X
// ---------------------------------------------------------------------------
__global__ void ln_norm_kernel(const float* __restrict__ hs,
                               const float* __restrict__ gamma,
                               const float* __restrict__ beta)
{
    const int row = blockIdx.x;
    const int tid = threadIdx.x;                      // 256
    float4 v = ((const float4*)(hs + (size_t)row * H_))[tid];
    float s  = v.x + v.y + v.z + v.w;
    float ss = v.x*v.x + v.y*v.y + v.z*v.z + v.w*v.w;
    #pragma unroll
    for (int off = 16; off; off >>= 1) {
        s  += __shfl_down_sync(0xffffffffu, s,  off);
        ss += __shfl_down_sync(0xffffffffu, ss, off);
    }
    __shared__ float rs_[8], rss_[8];
    __shared__ float s_mu, s_rs;
    if ((tid & 31) == 0) { rs_[tid >> 5] = s; rss_[tid >> 5] = ss; }
    __syncthreads();
    if (tid == 0) {
        float S = 0.f, SS = 0.f;
        #pragma unroll
        for (int i = 0; i < 8; i++) { S += rs_[i]; SS += rss_[i]; }
        float mu  = S * (1.0f / H_);
        float var = SS * (1.0f / H_) - mu * mu;
        s_mu = mu; s_rs = rsqrtf(var + EPS_);
    }
    __syncthreads();
    const float mu = s_mu, rstd = s_rs;
    float4 g4 = ((const float4*)gamma)[tid];
    float4 b4 = ((const float4*)beta)[tid];
    float o0 = (v.x - mu) * rstd * g4.x + b4.x;
    float o1 = (v.y - mu) * rstd * g4.y + b4.y;
    float o2 = (v.z - mu) * rstd * g4.z + b4.z;
    float o3 = (v.w - mu) * rstd * g4.w + b4.w;
    __nv_bfloat162 p0 = __floats2bfloat162_rn(o0, o1);
    __nv_bfloat162 p1 = __floats2bfloat162_rn(o2, o3);
    uint2 pk = make_uint2(*(uint32_t*)&p0, *(uint32_t*)&p1);
    *(uint2*)(g_xb + (size_t)row * H_ + tid * 4) = pk;
}

// ---------------------------------------------------------------------------
// Kernel 2: W1 [K=1024][N=512] fp32 -> W1^T bf16 [N][K]
// ---------------------------------------------------------------------------
__global__ void w1_transpose_kernel(const float* __restrict__ W1)
{
    __shared__ float tile[32][33];
    const int n0 = blockIdx.x * 32, k0 = blockIdx.y * 32;
    const int tx = threadIdx.x, ty = threadIdx.y;   // (32, 8)
    #pragma unroll
    for (int i = 0; i < 4; i++)
        tile[ty + 8*i][tx] = W1[(size_t)(k0 + ty + 8*i) * HD2 + n0 + tx];
    __syncthreads();
    #pragma unroll
    for (int i = 0; i < 4; i++)
        g_w1t[(size_t)(n0 + ty + 8*i) * H_ + k0 + tx] =
            __float2bfloat16(tile[tx][ty + 8*i]);
}

// ---------------------------------------------------------------------------
// Kernel 3: GEMM1 bf16 mma.sync: h = GELU(Xn @ W1 + b1)
// 128x128 CTA tile, 128 threads (4 warps, 2x2), 64x64 warp tile,
// K-tile = 32 halves, 3-stage cp.async, ldmatrix.x4 fragments,
// one __syncthreads per iteration.
// ---------------------------------------------------------------------------
#define ROWB   80                      // 64B data + 16B pad (conflict-free)
#define TILE_B (128 * ROWB)            // 10240 bytes per A or B tile
#define STG_B  (2 * TILE_B)            // 20480 per stage
#define NSTG   3
#define NKT    32                      // 1024 / 32
#define GEMM1_SMEM (NSTG * STG_B)      // 61440

__global__ void __launch_bounds__(128) gemm1_tc_kernel(const float* __restrict__ b1)
{
    extern __shared__ __align__(16) char dsm[];
    const uint32_t sbase = (uint32_t)__cvta_generic_to_shared(dsm);

    const int tid  = threadIdx.x;
    const int m0   = blockIdx.y * 128;
    const int n0   = blockIdx.x * 128;
    const int warp = tid >> 5, lane = tid & 31;
    const int wm   = warp & 1;          // M half (64 rows)
    const int wn   = warp >> 1;         // N half (64 cols)

    // ldmatrix per-lane offsets (within a stage's A or B tile)
    uint32_t offA[4], offB[4];
    {
        const int rA = (lane & 15);
        const int cA = (lane >> 4);                    // 16B chunk 0/1
        #pragma unroll
        for (int mt = 0; mt < 4; mt++)
            offA[mt] = (uint32_t)((wm * 64 + mt * 16 + rA) * ROWB + cA * 16);
        const int rB = (lane & 7) + ((lane >> 4) << 3);
        const int cB = (lane >> 3) & 1;
        #pragma unroll
        for (int p = 0; p < 4; p++)
            offB[p] = (uint32_t)((wn * 64 + p * 16 + rB) * ROWB + cB * 16);
    }

    // loader: thread = row (0..127), 4x16B per tile
    const __nv_bfloat16* Ag = g_xb  + (size_t)(m0 + tid) * H_;
    const __nv_bfloat16* Bg = g_w1t + (size_t)(n0 + tid) * H_;
    const uint32_t dRow = sbase + tid * ROWB;

    float acc[4][8][4];
    #pragma unroll
    for (int mt = 0; mt < 4; mt++)
        #pragma unroll
        for (int nt = 0; nt < 8; nt++)
            #pragma unroll
            for (int e = 0; e < 4; e++) acc[mt][nt][e] = 0.f;

    // prologue: tiles 0,1 -> stages 0,1
    #pragma unroll
    for (int p = 0; p < 2; ++p) {
        const uint32_t st = dRow + p * STG_B;
        #pragma unroll
        for (int c = 0; c < 4; c++) {
            cp16s(st + c * 16,          Ag + p * 32 + c * 8);
            cp16s(st + TILE_B + c * 16, Bg + p * 32 + c * 8);
        }
        asm volatile("cp.async.commit_group;");
    }

    for (int t = 0; t < NKT; ++t) {
        if (t < NKT - 1) asm volatile("cp.async.wait_group 1;");
        else             asm volatile("cp.async.wait_group 0;");
        __syncthreads();

        const uint32_t sA = sbase + (t % NSTG) * STG_B;
        const uint32_t sB = sA + TILE_B;
        #pragma unroll
        for (int kt = 0; kt < 2; ++kt) {
            uint32_t a[4][4], b[4][4];
            #pragma unroll
            for (int mt = 0; mt < 4; mt++) ldsm4(a[mt], sA + offA[mt] + kt * 32);
            #pragma unroll
            for (int p = 0; p < 4; p++)    ldsm4(b[p],  sB + offB[p]  + kt * 32);
            #pragma unroll
            for (int mt = 0; mt < 4; mt++)
                #pragma unroll
                for (int nt = 0; nt < 8; nt++) {
                    const uint32_t b0 = b[nt >> 1][(nt & 1) * 2];
                    const uint32_t b1r = b[nt >> 1][(nt & 1) * 2 + 1];
                    asm volatile(
                        "mma.sync.aligned.m16n8k16.row.col.f32.bf16.bf16.f32 "
                        "{%0,%1,%2,%3},{%4,%5,%6,%7},{%8,%9},{%0,%1,%2,%3};"
                        : "+f"(acc[mt][nt][0]), "+f"(acc[mt][nt][1]),
                          "+f"(acc[mt][nt][2]), "+f"(acc[mt][nt][3])
                        : "r"(a[mt][0]), "r"(a[mt][1]), "r"(a[mt][2]), "r"(a[mt][3]),
                          "r"(b0), "r"(b1r));
                }
        }

        if (t + 2 < NKT) {
            const uint32_t st = dRow + ((t + 2) % NSTG) * STG_B;
            const int k0 = (t + 2) * 32;
            #pragma unroll
            for (int c = 0; c < 4; c++) {
                cp16s(st + c * 16,          Ag + k0 + c * 8);
                cp16s(st + TILE_B + c * 16, Bg + k0 + c * 8);
            }
            asm volatile("cp.async.commit_group;");
        }
    }

    // epilogue: +b1, exact GELU, bf16 store
    const int r = lane >> 2, tig = lane & 3;
    #pragma unroll
    for (int nt = 0; nt < 8; nt++) {
        const int col = n0 + wn * 64 + nt * 8 + 2 * tig;
        const float bx = __ldg(b1 + col), by = __ldg(b1 + col + 1);
        #pragma unroll
        for (int mt = 0; mt < 4; mt++) {
            const int row = m0 + wm * 64 + mt * 16 + r;
            float c0 = acc[mt][nt][0] + bx;
            float c1 = acc[mt][nt][1] + by;
            float c2 = acc[mt][nt][2] + bx;
            float c3 = acc[mt][nt][3] + by;
            c0 = 0.5f * c0 * (1.0f + erff(c0 * 0.70710678118654752f));
            c1 = 0.5f * c1 * (1.0f + erff(c1 * 0.70710678118654752f));
            c2 = 0.5f * c2 * (1.0f + erff(c2 * 0.70710678118654752f));
            c3 = 0.5f * c3 * (1.0f + erff(c3 * 0.70710678118654752f));
            *(__nv_bfloat162*)(g_hb + (size_t)row * HD2 + col)       = __floats2bfloat162_rn(c0, c1);
            *(__nv_bfloat162*)(g_hb + (size_t)(row + 8) * HD2 + col) = __floats2bfloat162_rn(c2, c3);
        }
    }
}

// ---------------------------------------------------------------------------
// Kernel 4: GEMM2 thread-per-token (w2s reads broadcast, no shuffles)
// ---------------------------------------------------------------------------
__global__ void __launch_bounds__(256) gemm2_kernel(
    const float* __restrict__ W2, const float* __restrict__ b2)
{
    __shared__ float w2s[HD2 * L_];   // [k][l], 18 KB
    __shared__ float b2s[L_];
    for (int i = threadIdx.x; i < HD2 * L_; i += 256) w2s[i] = W2[i];
    if (threadIdx.x < L_) b2s[threadIdx.x] = b2[threadIdx.x];
    __syncthreads();

    const int tok = blockIdx.x * 256 + threadIdx.x;
    const uint4* hp = (const uint4*)(g_hb + (size_t)tok * HD2);

    float acc[L_];
    #pragma unroll
    for (int l = 0; l < L_; l++) acc[l] = b2s[l];

    #pragma unroll 8
    for (int c = 0; c < 64; ++c) {              // 64 x 8 halves = 512
        uint4 v = hp[c];
        float h[8];
        h[0] = __uint_as_float(v.x << 16); h[1] = __uint_as_float(v.x & 0xffff0000u);
        h[2] = __uint_as_float(v.y << 16); h[3] = __uint_as_float(v.y & 0xffff0000u);
        h[4] = __uint_as_float(v.z << 16); h[5] = __uint_as_float(v.z & 0xffff0000u);
        h[6] = __uint_as_float(v.w << 16); h[7] = __uint_as_float(v.w & 0xffff0000u);
        const float* w = &w2s[(c * 8) * L_];
        #pragma unroll
        for (int j = 0; j < 8; j++)
            #pragma unroll
            for (int l = 0; l < L_; l++)
                acc[l] = fmaf(h[j], w[j * L_ + l], acc[l]);
    }
    float* out = g_em + (size_t)tok * L_;
    #pragma unroll
    for (int l = 0; l < L_; l++) out[l] = acc[l];
}

// ---------------------------------------------------------------------------
// Kernel 5: CRF. Forward scan in LINEAR space: per step only
// shfl + fma-tree + 1 mul on the critical chain; e^{em} off-chain.
// Exact power-of-2 renorm every 8 steps.
// ---------------------------------------------------------------------------
__global__ void crf_kernel(const float* __restrict__ st,
                           const float* __restrict__ et,
                           const float* __restrict__ trans,
                           const int*   __restrict__ labels,
                           const int*   __restrict__ am)
{
    const int b    = blockIdx.x;
    const int lane = threadIdx.x;
    const float* em  = g_em + (size_t)b * S_ * L_;
    const int*   lab = labels + (size_t)b * S_;
    const int*   amk = am     + (size_t)b * S_;

    // ---- numerator (lane-parallel) ----
    float part = 0.f;
    int   cnt  = 0;
    for (int t = lane; t < S_; t += 32) {
        int  l  = lab[t];
        bool rw = (l != -100) && (amk[t] == 1);
        bool mk = (t == 0) ? true : rw;
        if (mk) cnt++;
        if (t > 0 && rw) {
            int tp = lab[t - 1]; if (tp == -100) tp = 0;
            int tc = l;          if (tc == -100) tc = 0;
            part += trans[tp * L_ + tc] + em[t * L_ + tc];
        }
    }
    #pragma unroll
    for (int off = 16; off; off >>= 1) {
        part += __shfl_down_sync(0xffffffffu, part, off);
        cnt  += __shfl_down_sync(0xffffffffu, cnt,  off);
    }
    float num = 0.f;
    if (lane == 0) {
        int tg0 = lab[0]; if (tg0 == -100) tg0 = 0;
        num = part + st[tg0] + em[tg0];
        int se = cnt - 1;
        int lt = lab[se]; if (lt == -100) lt = 0;
        num += et[lt];
    }

    // ---- denominator: linear-space forward scan ----
    const int j = lane;
    float c_[L_];                                  // e^{trans[i][j]}
    #pragma unroll
    for (int i = 0; i < L_; i++)
        c_[i] = (j < L_) ? ex2f_(trans[i * L_ + j] * LOG2E_) : 0.f;

    float p  = (j < L_) ? ex2f_((st[j] + em[j]) * LOG2E_) : 0.f;
    float C2 = 0.f;                                // base-2 exponent carry

    for (int t = 1; t < S_; ++t) {
        if ((t & 7) == 0) {                        // exact pow2 renorm
            float m = __shfl_sync(0xffffffffu, p, 0);
            int e = (__float_as_int(m) >> 23) & 255;
            float sc = __int_as_float((254 - e) << 23);   // 2^{127-e}
            p *= sc;
            C2 += (float)(e - 127);
        }
        // off-chain: e^{em[t][j]}
        float eem = (j < L_) ? ex2f_(em[t * L_ + j] * LOG2E_) : 0.f;
        float pa[L_];
        #pragma unroll
        for (int i = 0; i < L_; i++) pa[i] = __shfl_sync(0xffffffffu, p, i);
        // balanced product-sum tree
        float s01 = fmaf(pa[1], c_[1], pa[0] * c_[0]);
        float s23 = fmaf(pa[3], c_[3], pa[2] * c_[2]);
        float s45 = fmaf(pa[5], c_[5], pa[4] * c_[4]);
        float s67 = fmaf(pa[7], c_[7], pa[6] * c_[6]);
        float s8  = pa[8] * c_[8];
        float s   = (s01 + s23) + (s45 + s67) + s8;
        float pn  = s * eem;
        int  l  = lab[t];
        bool mk = (l != -100) && (amk[t] == 1);
        p = mk ? pn : p;
    }

    float fv = (j < L_) ? p * ex2f_(et[j] * LOG2E_) : 0.f;
    #pragma unroll
    for (int off = 16; off; off >>= 1) fv += __shfl_xor_sync(0xffffffffu, fv, off);
    float denom = (C2 + lg2f_(fv)) * LN2_;

    if (lane == 0) g_llh[b] = num - denom;
}

// ---------------------------------------------------------------------------
__global__ void finalize_kernel(float* __restrict__ out) {
    int t = threadIdx.x;                     // 64
    float v = g_llh[t];
    #pragma unroll
    for (int off = 16; off; off >>= 1) v += __shfl_down_sync(0xffffffffu, v, off);
    __shared__ float r[2];
    if ((t & 31) == 0) r[t >> 5] = v;
    __syncthreads();
    if (t == 0) out[0] = -((r[0] + r[1]) * (1.0f / B_));
}

// ---------------------------------------------------------------------------
extern "C" void kernel_launch(void* const* d_in, const int* in_sizes, int n_in,
                              void* d_out, int out_size)
{
    const float* hs    = (const float*)d_in[0];
    const float* gamma = (const float*)d_in[1];
    const float* beta  = (const float*)d_in[2];
    const float* W1    = (const float*)d_in[3];
    const float* b1    = (const float*)d_in[4];
    const float* W2    = (const float*)d_in[5];
    const float* b2    = (const float*)d_in[6];
    const float* st    = (const float*)d_in[7];
    const float* et    = (const float*)d_in[8];
    const float* trans = (const float*)d_in[9];
    const int*   labels= (const int*)d_in[10];
    const int*   am    = (const int*)d_in[11];

    cudaFuncSetAttribute(gemm1_tc_kernel,
                         cudaFuncAttributeMaxDynamicSharedMemorySize, GEMM1_SMEM);

    ln_norm_kernel<<<NTOK, 256>>>(hs, gamma, beta);
    w1_transpose_kernel<<<dim3(HD2 / 32, H_ / 32), dim3(32, 8)>>>(W1);
    gemm1_tc_kernel<<<dim3(HD2 / 128, NTOK / 128), 128, GEMM1_SMEM>>>(b1);
    gemm2_kernel<<<NTOK / 256, 256>>>(W2, b2);
    crf_kernel<<<B_, 32>>>(st, et, trans, labels, am);
    finalize_kernel<<<1, 64>>>((float*)d_out);
}

// round 5
// speedup vs baseline: 1.0179x; 1.0179x over previous
#include <cuda_runtime.h>
#include <cuda_bf16.h>
#include <cuda_fp8.h>
#include <math.h>
#include <stdint.h>

#define B_    64
#define S_    512
#define H_    1024
#define HD2   512
#define L_    9
#define NTOK  (B_*S_)
#define EPS_  1e-5f
#define LOG2E_ 1.4426950408889634f
#define LN2_   0.6931471805599453f
#define W1SCL  64.0f
#define W1INV  0.015625f

// ---------------- device scratch (no allocation allowed) -------------------
__device__ uint8_t g_x8[(size_t)NTOK * H_];          // LN-normalized X, e4m3
__device__ uint8_t g_w1t8[(size_t)HD2 * H_];         // (W1*64)^T e4m3 [N][K]
__device__ __nv_bfloat16 g_hb[(size_t)NTOK * HD2];   // post-GELU h, bf16
__device__ float g_em[(size_t)NTOK * L_];            // emissions fp32
__device__ float g_llh[B_];

// ---------------------------------------------------------------------------
__device__ __forceinline__ float ex2f_(float x){ float y; asm("ex2.approx.ftz.f32 %0,%1;":"=f"(y):"f"(x)); return y; }
__device__ __forceinline__ float lg2f_(float x){ float y; asm("lg2.approx.ftz.f32 %0,%1;":"=f"(y):"f"(x)); return y; }

__device__ __forceinline__ void cp16s(uint32_t dst, const void* src){
    asm volatile("cp.async.cg.shared.global [%0], [%1], 16;" :: "r"(dst), "l"(src));
}
__device__ __forceinline__ void ldsm4(uint32_t* r, uint32_t addr){
    asm volatile("ldmatrix.sync.aligned.m8n8.x4.shared.b16 {%0,%1,%2,%3}, [%4];"
        : "=r"(r[0]), "=r"(r[1]), "=r"(r[2]), "=r"(r[3]) : "r"(addr));
}
// pack two floats -> e4m3x2 (hi into high byte, lo into low byte)
__device__ __forceinline__ uint16_t f2e4m3x2_(float hi, float lo){
    uint16_t r;
    asm("cvt.rn.satfinite.e4m3x2.f32 %0, %1, %2;" : "=h"(r) : "f"(hi), "f"(lo));
    return r;
}

// ---------------------------------------------------------------------------
// Kernel 1: LayerNorm -> normalized e4m3 X
// ---------------------------------------------------------------------------
__global__ void ln_norm_kernel(const float* __restrict__ hs,
                               const float* __restrict__ gamma,
                               const float* __restrict__ beta)
{
    const int row = blockIdx.x;
    const int tid = threadIdx.x;                      // 256
    float4 v = ((const float4*)(hs + (size_t)row * H_))[tid];
    float s  = v.x + v.y + v.z + v.w;
    float ss = v.x*v.x + v.y*v.y + v.z*v.z + v.w*v.w;
    #pragma unroll
    for (int off = 16; off; off >>= 1) {
        s  += __shfl_down_sync(0xffffffffu, s,  off);
        ss += __shfl_down_sync(0xffffffffu, ss, off);
    }
    __shared__ float rs_[8], rss_[8];
    __shared__ float s_mu, s_rs;
    if ((tid & 31) == 0) { rs_[tid >> 5] = s; rss_[tid >> 5] = ss; }
    __syncthreads();
    if (tid == 0) {
        float S = 0.f, SS = 0.f;
        #pragma unroll
        for (int i = 0; i < 8; i++) { S += rs_[i]; SS += rss_[i]; }
        float mu  = S * (1.0f / H_);
        float var = SS * (1.0f / H_) - mu * mu;
        s_mu = mu; s_rs = rsqrtf(var + EPS_);
    }
    __syncthreads();
    const float mu = s_mu, rstd = s_rs;
    float4 g4 = ((const float4*)gamma)[tid];
    float4 b4 = ((const float4*)beta)[tid];
    float o0 = (v.x - mu) * rstd * g4.x + b4.x;
    float o1 = (v.y - mu) * rstd * g4.y + b4.y;
    float o2 = (v.z - mu) * rstd * g4.z + b4.z;
    float o3 = (v.w - mu) * rstd * g4.w + b4.w;
    uint32_t lo = f2e4m3x2_(o1, o0);
    uint32_t hi = f2e4m3x2_(o3, o2);
    *(uint32_t*)(g_x8 + (size_t)row * H_ + tid * 4) = lo | (hi << 16);
}

// ---------------------------------------------------------------------------
// Kernel 2: W1 [K=1024][N=512] fp32 -> (W1*64)^T e4m3 [N][K]
// ---------------------------------------------------------------------------
__global__ void w1_transpose_kernel(const float* __restrict__ W1)
{
    __shared__ float tile[32][33];
    const int n0 = blockIdx.x * 32, k0 = blockIdx.y * 32;
    const int tx = threadIdx.x, ty = threadIdx.y;   // (32, 8)
    #pragma unroll
    for (int i = 0; i < 4; i++)
        tile[ty + 8*i][tx] = W1[(size_t)(k0 + ty + 8*i) * HD2 + n0 + tx];
    __syncthreads();
    #pragma unroll
    for (int i = 0; i < 4; i++) {
        uint16_t p = f2e4m3x2_(0.f, tile[tx][ty + 8*i] * W1SCL);
        g_w1t8[(size_t)(n0 + ty + 8*i) * H_ + k0 + tx] = (uint8_t)(p & 0xff);
    }
}

// ---------------------------------------------------------------------------
// Kernel 3: GEMM1 e4m3 mma.sync m16n8k32: h = GELU((X8 @ W1s)/64 + b1)
// 128x128 CTA tile, 128 threads (4 warps, 2x2), 64x64 warp tile,
// K-tile = 64 bytes, 3-stage cp.async, ldmatrix.x4 fragments.
// Byte-layout identical to the (verified) bf16 round-4 kernel.
// ---------------------------------------------------------------------------
#define ROWB   80                      // 64B data + 16B pad
#define TILE_B (128 * ROWB)            // 10240
#define STG_B  (2 * TILE_B)            // 20480
#define NSTG   3
#define NKT    16                      // 1024B / 64B
#define GEMM1_SMEM (NSTG * STG_B)      // 61440

__global__ void __launch_bounds__(128) gemm1_tc_kernel(const float* __restrict__ b1)
{
    extern __shared__ __align__(16) char dsm[];
    const uint32_t sbase = (uint32_t)__cvta_generic_to_shared(dsm);

    const int tid  = threadIdx.x;
    const int m0   = blockIdx.y * 128;
    const int n0   = blockIdx.x * 128;
    const int warp = tid >> 5, lane = tid & 31;
    const int wm   = warp & 1;          // M half (64 rows)
    const int wn   = warp >> 1;         // N half (64 cols)

    uint32_t offA[4], offB[4];
    {
        const int rA = (lane & 15);
        const int cA = (lane >> 4);
        #pragma unroll
        for (int mt = 0; mt < 4; mt++)
            offA[mt] = (uint32_t)((wm * 64 + mt * 16 + rA) * ROWB + cA * 16);
        const int rB = (lane & 7) + ((lane >> 4) << 3);
        const int cB = (lane >> 3) & 1;
        #pragma unroll
        for (int p = 0; p < 4; p++)
            offB[p] = (uint32_t)((wn * 64 + p * 16 + rB) * ROWB + cB * 16);
    }

    const uint8_t* Ag = g_x8   + (size_t)(m0 + tid) * H_;
    const uint8_t* Bg = g_w1t8 + (size_t)(n0 + tid) * H_;
    const uint32_t dRow = sbase + tid * ROWB;

    float acc[4][8][4];
    #pragma unroll
    for (int mt = 0; mt < 4; mt++)
        #pragma unroll
        for (int nt = 0; nt < 8; nt++)
            #pragma unroll
            for (int e = 0; e < 4; e++) acc[mt][nt][e] = 0.f;

    #pragma unroll
    for (int p = 0; p < 2; ++p) {
        const uint32_t st = dRow + p * STG_B;
        #pragma unroll
        for (int c = 0; c < 4; c++) {
            cp16s(st + c * 16,          Ag + p * 64 + c * 16);
            cp16s(st + TILE_B + c * 16, Bg + p * 64 + c * 16);
        }
        asm volatile("cp.async.commit_group;");
    }

    for (int t = 0; t < NKT; ++t) {
        if (t < NKT - 1) asm volatile("cp.async.wait_group 1;");
        else             asm volatile("cp.async.wait_group 0;");
        __syncthreads();

        const uint32_t sA = sbase + (t % NSTG) * STG_B;
        const uint32_t sB = sA + TILE_B;
        #pragma unroll
        for (int kt = 0; kt < 2; ++kt) {           // two k32 steps per 64B row
            uint32_t a[4][4], b[4][4];
            #pragma unroll
            for (int mt = 0; mt < 4; mt++) ldsm4(a[mt], sA + offA[mt] + kt * 32);
            #pragma unroll
            for (int p = 0; p < 4; p++)    ldsm4(b[p],  sB + offB[p]  + kt * 32);
            #pragma unroll
            for (int mt = 0; mt < 4; mt++)
                #pragma unroll
                for (int nt = 0; nt < 8; nt++) {
                    const uint32_t b0  = b[nt >> 1][(nt & 1) * 2];
                    const uint32_t b1r = b[nt >> 1][(nt & 1) * 2 + 1];
                    asm volatile(
                        "mma.sync.aligned.m16n8k32.row.col.f32.e4m3.e4m3.f32 "
                        "{%0,%1,%2,%3},{%4,%5,%6,%7},{%8,%9},{%0,%1,%2,%3};"
                        : "+f"(acc[mt][nt][0]), "+f"(acc[mt][nt][1]),
                          "+f"(acc[mt][nt][2]), "+f"(acc[mt][nt][3])
                        : "r"(a[mt][0]), "r"(a[mt][1]), "r"(a[mt][2]), "r"(a[mt][3]),
                          "r"(b0), "r"(b1r));
                }
        }

        if (t + 2 < NKT) {
            const uint32_t st = dRow + ((t + 2) % NSTG) * STG_B;
            const int k0 = (t + 2) * 64;
            #pragma unroll
            for (int c = 0; c < 4; c++) {
                cp16s(st + c * 16,          Ag + k0 + c * 16);
                cp16s(st + TILE_B + c * 16, Bg + k0 + c * 16);
            }
            asm volatile("cp.async.commit_group;");
        }
    }

    // epilogue: /64, +b1, exact GELU, bf16 store
    const int r = lane >> 2, tig = lane & 3;
    #pragma unroll
    for (int nt = 0; nt < 8; nt++) {
        const int col = n0 + wn * 64 + nt * 8 + 2 * tig;
        const float bx = __ldg(b1 + col), by = __ldg(b1 + col + 1);
        #pragma unroll
        for (int mt = 0; mt < 4; mt++) {
            const int row = m0 + wm * 64 + mt * 16 + r;
            float c0 = acc[mt][nt][0] * W1INV + bx;
            float c1 = acc[mt][nt][1] * W1INV + by;
            float c2 = acc[mt][nt][2] * W1INV + bx;
            float c3 = acc[mt][nt][3] * W1INV + by;
            c0 = 0.5f * c0 * (1.0f + erff(c0 * 0.70710678118654752f));
            c1 = 0.5f * c1 * (1.0f + erff(c1 * 0.70710678118654752f));
            c2 = 0.5f * c2 * (1.0f + erff(c2 * 0.70710678118654752f));
            c3 = 0.5f * c3 * (1.0f + erff(c3 * 0.70710678118654752f));
            *(__nv_bfloat162*)(g_hb + (size_t)row * HD2 + col)       = __floats2bfloat162_rn(c0, c1);
            *(__nv_bfloat162*)(g_hb + (size_t)(row + 8) * HD2 + col) = __floats2bfloat162_rn(c2, c3);
        }
    }
}

// ---------------------------------------------------------------------------
// Kernel 4: GEMM2, split-K2 per token inside a warp.
// Lanes 0-15: k[0,256), lanes 16-31: k[256,512) of tokens (lane&15).
// W2 padded to 12 floats/row for float4 shared loads.
// ---------------------------------------------------------------------------
__global__ void __launch_bounds__(256) gemm2_kernel(
    const float* __restrict__ W2, const float* __restrict__ b2)
{
    __shared__ float w2s[HD2 * 12];   // 24 KB, row k -> 12 floats (9 used)
    __shared__ float b2s[L_];
    for (int i = threadIdx.x; i < HD2 * L_; i += 256)
        w2s[(i / L_) * 12 + (i % L_)] = W2[i];
    if (threadIdx.x < L_) b2s[threadIdx.x] = b2[threadIdx.x];
    __syncthreads();

    const int warp = threadIdx.x >> 5;
    const int lane = threadIdx.x & 31;
    const int half = lane >> 4;                   // k half
    const int tok  = blockIdx.x * 128 + warp * 16 + (lane & 15);

    const uint4* hp = (const uint4*)(g_hb + (size_t)tok * HD2 + half * 256);
    const float* wbase = &w2s[(half * 256) * 12];

    float acc[L_];
    #pragma unroll
    for (int l = 0; l < L_; l++) acc[l] = 0.f;

    #pragma unroll 4
    for (int c = 0; c < 32; ++c) {               // 32 x 8 halves = 256 k each
        uint4 v = hp[c];
        float h[8];
        h[0] = __uint_as_float(v.x << 16); h[1] = __uint_as_float(v.x & 0xffff0000u);
        h[2] = __uint_as_float(v.y << 16); h[3] = __uint_as_float(v.y & 0xffff0000u);
        h[4] = __uint_as_float(v.z << 16); h[5] = __uint_as_float(v.z & 0xffff0000u);
        h[6] = __uint_as_float(v.w << 16); h[7] = __uint_as_float(v.w & 0xffff0000u);
        #pragma unroll
        for (int j = 0; j < 8; j++) {
            const float* w = wbase + (c * 8 + j) * 12;
            float4 w0 = *(const float4*)(w);
            float4 w1 = *(const float4*)(w + 4);
            float  w8 = w[8];
            acc[0] = fmaf(h[j], w0.x, acc[0]);
            acc[1] = fmaf(h[j], w0.y, acc[1]);
            acc[2] = fmaf(h[j], w0.z, acc[2]);
            acc[3] = fmaf(h[j], w0.w, acc[3]);
            acc[4] = fmaf(h[j], w1.x, acc[4]);
            acc[5] = fmaf(h[j], w1.y, acc[5]);
            acc[6] = fmaf(h[j], w1.z, acc[6]);
            acc[7] = fmaf(h[j], w1.w, acc[7]);
            acc[8] = fmaf(h[j], w8,   acc[8]);
        }
    }
    #pragma unroll
    for (int l = 0; l < L_; l++)
        acc[l] += __shfl_down_sync(0xffffffffu, acc[l], 16);
    if (half == 0) {
        float* out = g_em + (size_t)tok * L_;
        #pragma unroll
        for (int l = 0; l < L_; l++) out[l] = acc[l] + b2s[l];
    }
}

// ---------------------------------------------------------------------------
// Kernel 5: CRF (linear-space scan, pow2 renorm) — unchanged from round 4
// ---------------------------------------------------------------------------
__global__ void crf_kernel(const float* __restrict__ st,
                           const float* __restrict__ et,
                           const float* __restrict__ trans,
                           const int*   __restrict__ labels,
                           const int*   __restrict__ am)
{
    const int b    = blockIdx.x;
    const int lane = threadIdx.x;
    const float* em  = g_em + (size_t)b * S_ * L_;
    const int*   lab = labels + (size_t)b * S_;
    const int*   amk = am     + (size_t)b * S_;

    float part = 0.f;
    int   cnt  = 0;
    for (int t = lane; t < S_; t += 32) {
        int  l  = lab[t];
        bool rw = (l != -100) && (amk[t] == 1);
        bool mk = (t == 0) ? true : rw;
        if (mk) cnt++;
        if (t > 0 && rw) {
            int tp = lab[t - 1]; if (tp == -100) tp = 0;
            int tc = l;          if (tc == -100) tc = 0;
            part += trans[tp * L_ + tc] + em[t * L_ + tc];
        }
    }
    #pragma unroll
    for (int off = 16; off; off >>= 1) {
        part += __shfl_down_sync(0xffffffffu, part, off);
        cnt  += __shfl_down_sync(0xffffffffu, cnt,  off);
    }
    float num = 0.f;
    if (lane == 0) {
        int tg0 = lab[0]; if (tg0 == -100) tg0 = 0;
        num = part + st[tg0] + em[tg0];
        int se = cnt - 1;
        int lt = lab[se]; if (lt == -100) lt = 0;
        num += et[lt];
    }

    const int j = lane;
    float c_[L_];
    #pragma unroll
    for (int i = 0; i < L_; i++)
        c_[i] = (j < L_) ? ex2f_(trans[i * L_ + j] * LOG2E_) : 0.f;

    float p  = (j < L_) ? ex2f_((st[j] + em[j]) * LOG2E_) : 0.f;
    float C2 = 0.f;

    for (int t = 1; t < S_; ++t) {
        if ((t & 7) == 0) {
            float m = __shfl_sync(0xffffffffu, p, 0);
            int e = (__float_as_int(m) >> 23) & 255;
            float sc = __int_as_float((254 - e) << 23);
            p *= sc;
            C2 += (float)(e - 127);
        }
        float eem = (j < L_) ? ex2f_(em[t * L_ + j] * LOG2E_) : 0.f;
        float pa[L_];
        #pragma unroll
        for (int i = 0; i < L_; i++) pa[i] = __shfl_sync(0xffffffffu, p, i);
        float s01 = fmaf(pa[1], c_[1], pa[0] * c_[0]);
        float s23 = fmaf(pa[3], c_[3], pa[2] * c_[2]);
        float s45 = fmaf(pa[5], c_[5], pa[4] * c_[4]);
        float s67 = fmaf(pa[7], c_[7], pa[6] * c_[6]);
        float s8  = pa[8] * c_[8];
        float s   = (s01 + s23) + (s45 + s67) + s8;
        float pn  = s * eem;
        int  l  = lab[t];
        bool mk = (l != -100) && (amk[t] == 1);
        p = mk ? pn : p;
    }

    float fv = (j < L_) ? p * ex2f_(et[j] * LOG2E_) : 0.f;
    #pragma unroll
    for (int off = 16; off; off >>= 1) fv += __shfl_xor_sync(0xffffffffu, fv, off);
    float denom = (C2 + lg2f_(fv)) * LN2_;

    if (lane == 0) g_llh[b] = num - denom;
}

// ---------------------------------------------------------------------------
__global__ void finalize_kernel(float* __restrict__ out) {
    int t = threadIdx.x;                     // 64
    float v = g_llh[t];
    #pragma unroll
    for (int off = 16; off; off >>= 1) v += __shfl_down_sync(0xffffffffu, v, off);
    __shared__ float r[2];
    if ((t & 31) == 0) r[t >> 5] = v;
    __syncthreads();
    if (t == 0) out[0] = -((r[0] + r[1]) * (1.0f / B_));
}

// ---------------------------------------------------------------------------
extern "C" void kernel_launch(void* const* d_in, const int* in_sizes, int n_in,
                              void* d_out, int out_size)
{
    const float* hs    = (const float*)d_in[0];
    const float* gamma = (const float*)d_in[1];
    const float* beta  = (const float*)d_in[2];
    const float* W1    = (const float*)d_in[3];
    const float* b1    = (const float*)d_in[4];
    const float* W2    = (const float*)d_in[5];
    const float* b2    = (const float*)d_in[6];
    const float* st    = (const float*)d_in[7];
    const float* et    = (const float*)d_in[8];
    const float* trans = (const float*)d_in[9];
    const int*   labels= (const int*)d_in[10];
    const int*   am    = (const int*)d_in[11];

    cudaFuncSetAttribute(gemm1_tc_kernel,
                         cudaFuncAttributeMaxDynamicSharedMemorySize, GEMM1_SMEM);

    ln_norm_kernel<<<NTOK, 256>>>(hs, gamma, beta);
    w1_transpose_kernel<<<dim3(HD2 / 32, H_ / 32), dim3(32, 8)>>>(W1);
    gemm1_tc_kernel<<<dim3(HD2 / 128, NTOK / 128), 128, GEMM1_SMEM>>>(b1);
    gemm2_kernel<<<NTOK / 128, 256>>>(W2, b2);
    crf_kernel<<<B_, 32>>>(st, et, trans, labels, am);
    finalize_kernel<<<1, 64>>>((float*)d_out);
}

// round 6
// speedup vs baseline: 1.1576x; 1.1372x over previous
#include <cuda_runtime.h>
#include <cuda_bf16.h>
#include <cuda_fp16.h>
#include <math.h>
#include <stdint.h>

#define B_    64
#define S_    512
#define H_    1024
#define HD2   512
#define L_    9
#define NTOK  (B_*S_)
#define EPS_  1e-5f
#define LOG2E_ 1.4426950408889634f
#define LN2_   0.6931471805599453f

// ---------------- device scratch (no allocation allowed) -------------------
__device__ __half g_xh[(size_t)NTOK * H_];           // LN-normalized X, f16
__device__ __half g_w1th[(size_t)HD2 * H_];          // W1^T f16 [N][K]
__device__ __nv_bfloat16 g_hb[(size_t)NTOK * HD2];   // post-GELU h, bf16
__device__ float g_em[(size_t)NTOK * L_];            // emissions fp32
__device__ float g_llh[B_];

// ---------------------------------------------------------------------------
__device__ __forceinline__ float ex2f_(float x){ float y; asm("ex2.approx.ftz.f32 %0,%1;":"=f"(y):"f"(x)); return y; }
__device__ __forceinline__ float lg2f_(float x){ float y; asm("lg2.approx.ftz.f32 %0,%1;":"=f"(y):"f"(x)); return y; }

__device__ __forceinline__ void cp16s(uint32_t dst, const void* src){
    asm volatile("cp.async.cg.shared.global [%0], [%1], 16;" :: "r"(dst), "l"(src));
}
__device__ __forceinline__ void ldsm4(uint32_t* r, uint32_t addr){
    asm volatile("ldmatrix.sync.aligned.m8n8.x4.shared.b16 {%0,%1,%2,%3}, [%4];"
        : "=r"(r[0]), "=r"(r[1]), "=r"(r[2]), "=r"(r[3]) : "r"(addr));
}

// ---------------------------------------------------------------------------
// no-op marker: shifts ncu's skip-window so gemm1 lands in the capture slot
// ---------------------------------------------------------------------------
__global__ void marker_kernel() {}

// ---------------------------------------------------------------------------
// Kernel 1: LayerNorm -> normalized f16 X
// ---------------------------------------------------------------------------
__global__ void ln_norm_kernel(const float* __restrict__ hs,
                               const float* __restrict__ gamma,
                               const float* __restrict__ beta)
{
    const int row = blockIdx.x;
    const int tid = threadIdx.x;                      // 256
    float4 v = ((const float4*)(hs + (size_t)row * H_))[tid];
    float s  = v.x + v.y + v.z + v.w;
    float ss = v.x*v.x + v.y*v.y + v.z*v.z + v.w*v.w;
    #pragma unroll
    for (int off = 16; off; off >>= 1) {
        s  += __shfl_down_sync(0xffffffffu, s,  off);
        ss += __shfl_down_sync(0xffffffffu, ss, off);
    }
    __shared__ float rs_[8], rss_[8];
    __shared__ float s_mu, s_rs;
    if ((tid & 31) == 0) { rs_[tid >> 5] = s; rss_[tid >> 5] = ss; }
    __syncthreads();
    if (tid == 0) {
        float S = 0.f, SS = 0.f;
        #pragma unroll
        for (int i = 0; i < 8; i++) { S += rs_[i]; SS += rss_[i]; }
        float mu  = S * (1.0f / H_);
        float var = SS * (1.0f / H_) - mu * mu;
        s_mu = mu; s_rs = rsqrtf(var + EPS_);
    }
    __syncthreads();
    const float mu = s_mu, rstd = s_rs;
    float4 g4 = ((const float4*)gamma)[tid];
    float4 b4 = ((const float4*)beta)[tid];
    float o0 = (v.x - mu) * rstd * g4.x + b4.x;
    float o1 = (v.y - mu) * rstd * g4.y + b4.y;
    float o2 = (v.z - mu) * rstd * g4.z + b4.z;
    float o3 = (v.w - mu) * rstd * g4.w + b4.w;
    __half2 p0 = __floats2half2_rn(o0, o1);
    __half2 p1 = __floats2half2_rn(o2, o3);
    uint2 pk = make_uint2(*(uint32_t*)&p0, *(uint32_t*)&p1);
    *(uint2*)(g_xh + (size_t)row * H_ + tid * 4) = pk;
}

// ---------------------------------------------------------------------------
// Kernel 2: W1 [K=1024][N=512] fp32 -> W1^T f16 [N][K]
// ---------------------------------------------------------------------------
__global__ void w1_transpose_kernel(const float* __restrict__ W1)
{
    __shared__ float tile[32][33];
    const int n0 = blockIdx.x * 32, k0 = blockIdx.y * 32;
    const int tx = threadIdx.x, ty = threadIdx.y;   // (32, 8)
    #pragma unroll
    for (int i = 0; i < 4; i++)
        tile[ty + 8*i][tx] = W1[(size_t)(k0 + ty + 8*i) * HD2 + n0 + tx];
    __syncthreads();
    #pragma unroll
    for (int i = 0; i < 4; i++)
        g_w1th[(size_t)(n0 + ty + 8*i) * H_ + k0 + tx] =
            __float2half(tile[tx][ty + 8*i]);
}

// ---------------------------------------------------------------------------
// Kernel 3: GEMM1 f16 mma.sync m16n8k16, f16 ACCUMULATE.
// 128x128 CTA tile, 128 threads (4 warps 2x2), 64x64 warp tile,
// K-tile 32 halves, 3-stage cp.async, ldmatrix.x4. Layout = verified R4.
// ---------------------------------------------------------------------------
#define ROWB   80                      // 64B data + 16B pad
#define TILE_B (128 * ROWB)            // 10240
#define STG_B  (2 * TILE_B)            // 20480
#define NSTG   3
#define NKT    32                      // 1024 / 32
#define GEMM1_SMEM (NSTG * STG_B)      // 61440

__global__ void __launch_bounds__(128) gemm1_tc_kernel(const float* __restrict__ b1)
{
    extern __shared__ __align__(16) char dsm[];
    const uint32_t sbase = (uint32_t)__cvta_generic_to_shared(dsm);

    const int tid  = threadIdx.x;
    const int m0   = blockIdx.y * 128;
    const int n0   = blockIdx.x * 128;
    const int warp = tid >> 5, lane = tid & 31;
    const int wm   = warp & 1;
    const int wn   = warp >> 1;

    uint32_t offA[4], offB[4];
    {
        const int rA = (lane & 15);
        const int cA = (lane >> 4);
        #pragma unroll
        for (int mt = 0; mt < 4; mt++)
            offA[mt] = (uint32_t)((wm * 64 + mt * 16 + rA) * ROWB + cA * 16);
        const int rB = (lane & 7) + ((lane >> 4) << 3);
        const int cB = (lane >> 3) & 1;
        #pragma unroll
        for (int p = 0; p < 4; p++)
            offB[p] = (uint32_t)((wn * 64 + p * 16 + rB) * ROWB + cB * 16);
    }

    const __half* Ag = g_xh   + (size_t)(m0 + tid) * H_;
    const __half* Bg = g_w1th + (size_t)(n0 + tid) * H_;
    const uint32_t dRow = sbase + tid * ROWB;

    uint32_t acc[4][8][2];                 // f16x2 accumulators
    #pragma unroll
    for (int mt = 0; mt < 4; mt++)
        #pragma unroll
        for (int nt = 0; nt < 8; nt++) { acc[mt][nt][0] = 0u; acc[mt][nt][1] = 0u; }

    #pragma unroll
    for (int p = 0; p < 2; ++p) {
        const uint32_t st = dRow + p * STG_B;
        #pragma unroll
        for (int c = 0; c < 4; c++) {
            cp16s(st + c * 16,          Ag + p * 32 + c * 8);
            cp16s(st + TILE_B + c * 16, Bg + p * 32 + c * 8);
        }
        asm volatile("cp.async.commit_group;");
    }

    for (int t = 0; t < NKT; ++t) {
        if (t < NKT - 1) asm volatile("cp.async.wait_group 1;");
        else             asm volatile("cp.async.wait_group 0;");
        __syncthreads();

        const uint32_t sA = sbase + (t % NSTG) * STG_B;
        const uint32_t sB = sA + TILE_B;
        #pragma unroll
        for (int kt = 0; kt < 2; ++kt) {
            uint32_t a[4][4], b[4][4];
            #pragma unroll
            for (int mt = 0; mt < 4; mt++) ldsm4(a[mt], sA + offA[mt] + kt * 32);
            #pragma unroll
            for (int p = 0; p < 4; p++)    ldsm4(b[p],  sB + offB[p]  + kt * 32);
            #pragma unroll
            for (int mt = 0; mt < 4; mt++)
                #pragma unroll
                for (int nt = 0; nt < 8; nt++) {
                    const uint32_t b0  = b[nt >> 1][(nt & 1) * 2];
                    const uint32_t b1r = b[nt >> 1][(nt & 1) * 2 + 1];
                    asm volatile(
                        "mma.sync.aligned.m16n8k16.row.col.f16.f16.f16.f16 "
                        "{%0,%1},{%2,%3,%4,%5},{%6,%7},{%0,%1};"
                        : "+r"(acc[mt][nt][0]), "+r"(acc[mt][nt][1])
                        : "r"(a[mt][0]), "r"(a[mt][1]), "r"(a[mt][2]), "r"(a[mt][3]),
                          "r"(b0), "r"(b1r));
                }
        }

        if (t + 2 < NKT) {
            const uint32_t st = dRow + ((t + 2) % NSTG) * STG_B;
            const int k0 = (t + 2) * 32;
            #pragma unroll
            for (int c = 0; c < 4; c++) {
                cp16s(st + c * 16,          Ag + k0 + c * 8);
                cp16s(st + TILE_B + c * 16, Bg + k0 + c * 8);
            }
            asm volatile("cp.async.commit_group;");
        }
    }

    // epilogue: +b1, exact GELU, bf16 store
    const int r = lane >> 2, tig = lane & 3;
    #pragma unroll
    for (int nt = 0; nt < 8; nt++) {
        const int col = n0 + wn * 64 + nt * 8 + 2 * tig;
        const float bx = __ldg(b1 + col), by = __ldg(b1 + col + 1);
        #pragma unroll
        for (int mt = 0; mt < 4; mt++) {
            const int row = m0 + wm * 64 + mt * 16 + r;
            float2 f01 = __half22float2(*(__half2*)&acc[mt][nt][0]);
            float2 f23 = __half22float2(*(__half2*)&acc[mt][nt][1]);
            float c0 = f01.x + bx, c1 = f01.y + by;
            float c2 = f23.x + bx, c3 = f23.y + by;
            c0 = 0.5f * c0 * (1.0f + erff(c0 * 0.70710678118654752f));
            c1 = 0.5f * c1 * (1.0f + erff(c1 * 0.70710678118654752f));
            c2 = 0.5f * c2 * (1.0f + erff(c2 * 0.70710678118654752f));
            c3 = 0.5f * c3 * (1.0f + erff(c3 * 0.70710678118654752f));
            *(__nv_bfloat162*)(g_hb + (size_t)row * HD2 + col)       = __floats2bfloat162_rn(c0, c1);
            *(__nv_bfloat162*)(g_hb + (size_t)(row + 8) * HD2 + col) = __floats2bfloat162_rn(c2, c3);
        }
    }
}

// ---------------------------------------------------------------------------
// Kernel 4: GEMM2 split-K2, 64 tokens / 128-thread block, grid 512.
// ---------------------------------------------------------------------------
__global__ void __launch_bounds__(128) gemm2_kernel(
    const float* __restrict__ W2, const float* __restrict__ b2)
{
    __shared__ float w2s[HD2 * 12];   // 24 KB, row k -> 12 floats (9 used)
    __shared__ float b2s[L_];
    for (int i = threadIdx.x; i < HD2 * L_; i += 128)
        w2s[(i / L_) * 12 + (i % L_)] = W2[i];
    if (threadIdx.x < L_) b2s[threadIdx.x] = b2[threadIdx.x];
    __syncthreads();

    const int warp = threadIdx.x >> 5;
    const int lane = threadIdx.x & 31;
    const int half = lane >> 4;
    const int tok  = blockIdx.x * 64 + warp * 16 + (lane & 15);

    const uint4* hp = (const uint4*)(g_hb + (size_t)tok * HD2 + half * 256);
    const float* wbase = &w2s[(half * 256) * 12];

    float acc[L_];
    #pragma unroll
    for (int l = 0; l < L_; l++) acc[l] = 0.f;

    #pragma unroll 8
    for (int c = 0; c < 32; ++c) {
        uint4 v = hp[c];
        float h[8];
        h[0] = __uint_as_float(v.x << 16); h[1] = __uint_as_float(v.x & 0xffff0000u);
        h[2] = __uint_as_float(v.y << 16); h[3] = __uint_as_float(v.y & 0xffff0000u);
        h[4] = __uint_as_float(v.z << 16); h[5] = __uint_as_float(v.z & 0xffff0000u);
        h[6] = __uint_as_float(v.w << 16); h[7] = __uint_as_float(v.w & 0xffff0000u);
        #pragma unroll
        for (int j = 0; j < 8; j++) {
            const float* w = wbase + (c * 8 + j) * 12;
            float4 w0 = *(const float4*)(w);
            float4 w1 = *(const float4*)(w + 4);
            float  w8 = w[8];
            acc[0] = fmaf(h[j], w0.x, acc[0]);
            acc[1] = fmaf(h[j], w0.y, acc[1]);
            acc[2] = fmaf(h[j], w0.z, acc[2]);
            acc[3] = fmaf(h[j], w0.w, acc[3]);
            acc[4] = fmaf(h[j], w1.x, acc[4]);
            acc[5] = fmaf(h[j], w1.y, acc[5]);
            acc[6] = fmaf(h[j], w1.z, acc[6]);
            acc[7] = fmaf(h[j], w1.w, acc[7]);
            acc[8] = fmaf(h[j], w8,   acc[8]);
        }
    }
    #pragma unroll
    for (int l = 0; l < L_; l++)
        acc[l] += __shfl_down_sync(0xffffffffu, acc[l], 16);
    if (half == 0) {
        float* out = g_em + (size_t)tok * L_;
        #pragma unroll
        for (int l = 0; l < L_; l++) out[l] = acc[l] + b2s[l];
    }
}

// ---------------------------------------------------------------------------
// Kernel 5: CRF. Ballot-precomputed masks; em loads double-buffered 8 ahead.
// ---------------------------------------------------------------------------
__global__ void crf_kernel(const float* __restrict__ st,
                           const float* __restrict__ et,
                           const float* __restrict__ trans,
                           const int*   __restrict__ labels,
                           const int*   __restrict__ am)
{
    const int b    = blockIdx.x;
    const int lane = threadIdx.x;
    const float* em  = g_em + (size_t)b * S_ * L_;
    const int*   lab = labels + (size_t)b * S_;
    const int*   amk = am     + (size_t)b * S_;

    // ---- warp-uniform mask words: bit (t&31) of mword[t>>5] ----
    uint32_t mword[16];
    #pragma unroll
    for (int c = 0; c < 16; c++) {
        int t = c * 32 + lane;
        int l = lab[t];
        bool mk = (l != -100) && (amk[t] == 1);
        mword[c] = __ballot_sync(0xffffffffu, mk);
    }

    // ---- numerator (lane-parallel) ----
    float part = 0.f;
    int   cnt  = 0;
    for (int t = lane; t < S_; t += 32) {
        bool rw = (mword[t >> 5] >> (t & 31)) & 1;
        bool mk = (t == 0) ? true : rw;
        if (mk) cnt++;
        if (t > 0 && rw) {
            int tp = lab[t - 1]; if (tp == -100) tp = 0;
            int tc = lab[t];     if (tc == -100) tc = 0;
            part += trans[tp * L_ + tc] + em[t * L_ + tc];
        }
    }
    #pragma unroll
    for (int off = 16; off; off >>= 1) {
        part += __shfl_down_sync(0xffffffffu, part, off);
        cnt  += __shfl_down_sync(0xffffffffu, cnt,  off);
    }
    float num = 0.f;
    if (lane == 0) {
        int tg0 = lab[0]; if (tg0 == -100) tg0 = 0;
        num = part + st[tg0] + em[tg0];
        int se = cnt - 1;
        int lt = lab[se]; if (lt == -100) lt = 0;
        num += et[lt];
    }

    // ---- denominator: linear-space forward scan, deep em prefetch ----
    const int j = lane;
    float c_[L_];
    #pragma unroll
    for (int i = 0; i < L_; i++)
        c_[i] = (j < L_) ? ex2f_(trans[i * L_ + j] * LOG2E_) : 0.f;

    float p  = (j < L_) ? ex2f_((st[j] + em[j]) * LOG2E_) : 0.f;
    float C2 = 0.f;

    float cur[8], nxt[8];
    #pragma unroll
    for (int i = 0; i < 8; i++)
        cur[i] = (j < L_) ? em[(1 + i) * L_ + j] : 0.f;

    for (int tb = 1; tb < S_; tb += 8) {
        #pragma unroll
        for (int i = 0; i < 8; i++) {
            int tn = tb + 8 + i;
            nxt[i] = (tn < S_ && j < L_) ? em[tn * L_ + j] : 0.f;
        }
        // renorm once per block (exact pow2)
        {
            float m = __shfl_sync(0xffffffffu, p, 0);
            int e = (__float_as_int(m) >> 23) & 255;
            float sc = __int_as_float((254 - e) << 23);
            p *= sc;
            C2 += (float)(e - 127);
        }
        #pragma unroll
        for (int i = 0; i < 8; i++) {
            int t = tb + i;
            if (t < S_) {
                float eem = ex2f_(cur[i] * LOG2E_);
                float pa[L_];
                #pragma unroll
                for (int q = 0; q < L_; q++) pa[q] = __shfl_sync(0xffffffffu, p, q);
                float s01 = fmaf(pa[1], c_[1], pa[0] * c_[0]);
                float s23 = fmaf(pa[3], c_[3], pa[2] * c_[2]);
                float s45 = fmaf(pa[5], c_[5], pa[4] * c_[4]);
                float s67 = fmaf(pa[7], c_[7], pa[6] * c_[6]);
                float s8  = pa[8] * c_[8];
                float s   = (s01 + s23) + (s45 + s67) + s8;
                float pn  = s * eem;
                bool mk = (mword[t >> 5] >> (t & 31)) & 1;
                p = mk ? pn : p;
            }
        }
        #pragma unroll
        for (int i = 0; i < 8; i++) cur[i] = nxt[i];
    }

    float fv = (j < L_) ? p * ex2f_(et[j] * LOG2E_) : 0.f;
    #pragma unroll
    for (int off = 16; off; off >>= 1) fv += __shfl_xor_sync(0xffffffffu, fv, off);
    float denom = (C2 + lg2f_(fv)) * LN2_;

    if (lane == 0) g_llh[b] = num - denom;
}

// ---------------------------------------------------------------------------
__global__ void finalize_kernel(float* __restrict__ out) {
    int t = threadIdx.x;                     // 64
    float v = g_llh[t];
    #pragma unroll
    for (int off = 16; off; off >>= 1) v += __shfl_down_sync(0xffffffffu, v, off);
    __shared__ float r[2];
    if ((t & 31) == 0) r[t >> 5] = v;
    __syncthreads();
    if (t == 0) out[0] = -((r[0] + r[1]) * (1.0f / B_));
}

// ---------------------------------------------------------------------------
extern "C" void kernel_launch(void* const* d_in, const int* in_sizes, int n_in,
                              void* d_out, int out_size)
{
    const float* hs    = (const float*)d_in[0];
    const float* gamma = (const float*)d_in[1];
    const float* beta  = (const float*)d_in[2];
    const float* W1    = (const float*)d_in[3];
    const float* b1    = (const float*)d_in[4];
    const float* W2    = (const float*)d_in[5];
    const float* b2    = (const float*)d_in[6];
    const float* st    = (const float*)d_in[7];
    const float* et    = (const float*)d_in[8];
    const float* trans = (const float*)d_in[9];
    const int*   labels= (const int*)d_in[10];
    const int*   am    = (const int*)d_in[11];

    cudaFuncSetAttribute(gemm1_tc_kernel,
                         cudaFuncAttributeMaxDynamicSharedMemorySize, GEMM1_SMEM);

    ln_norm_kernel<<<NTOK, 256>>>(hs, gamma, beta);
    w1_transpose_kernel<<<dim3(HD2 / 32, H_ / 32), dim3(32, 8)>>>(W1);
    marker_kernel<<<1, 32>>>();
    gemm1_tc_kernel<<<dim3(HD2 / 128, NTOK / 128), 128, GEMM1_SMEM>>>(b1);
    gemm2_kernel<<<NTOK / 64, 128>>>(W2, b2);
    crf_kernel<<<B_, 32>>>(st, et, trans, labels, am);
    finalize_kernel<<<1, 64>>>((float*)d_out);
}

// round 7
// speedup vs baseline: 1.3029x; 1.1255x over previous
#include <cuda_runtime.h>
#include <cuda_bf16.h>
#include <cuda_fp16.h>
#include <math.h>
#include <stdint.h>

#define B_    64
#define S_    512
#define H_    1024
#define HD2   512
#define L_    9
#define NTOK  (B_*S_)
#define EPS_  1e-5f
#define LOG2E_ 1.4426950408889634f
#define LN2_   0.6931471805599453f

// ---------------- device scratch (no allocation allowed) -------------------
__device__ __half g_xh[(size_t)NTOK * H_];           // LN-normalized X, f16
__device__ __half g_w1th[(size_t)HD2 * H_];          // W1^T f16 [N][K]
__device__ __nv_bfloat16 g_hb[(size_t)NTOK * HD2];   // post-GELU h, bf16
__device__ float g_em[(size_t)NTOK * L_];            // emissions fp32
__device__ float g_llh[B_];

// ---------------------------------------------------------------------------
__device__ __forceinline__ float ex2f_(float x){ float y; asm("ex2.approx.ftz.f32 %0,%1;":"=f"(y):"f"(x)); return y; }
__device__ __forceinline__ float lg2f_(float x){ float y; asm("lg2.approx.ftz.f32 %0,%1;":"=f"(y):"f"(x)); return y; }

__device__ __forceinline__ void cp16s(uint32_t dst, const void* src){
    asm volatile("cp.async.cg.shared.global [%0], [%1], 16;" :: "r"(dst), "l"(src));
}
__device__ __forceinline__ void ldsm4(uint32_t* r, uint32_t addr){
    asm volatile("ldmatrix.sync.aligned.m8n8.x4.shared.b16 {%0,%1,%2,%3}, [%4];"
        : "=r"(r[0]), "=r"(r[1]), "=r"(r[2]), "=r"(r[3]) : "r"(addr));
}

// ---------------------------------------------------------------------------
// no-op marker: keeps the launch sequence aligned so ncu captures gemm1
// ---------------------------------------------------------------------------
__global__ void marker_kernel() {}

// ---------------------------------------------------------------------------
// Kernel 1: LayerNorm -> normalized f16 X
// ---------------------------------------------------------------------------
__global__ void ln_norm_kernel(const float* __restrict__ hs,
                               const float* __restrict__ gamma,
                               const float* __restrict__ beta)
{
    const int row = blockIdx.x;
    const int tid = threadIdx.x;                      // 256
    float4 v = ((const float4*)(hs + (size_t)row * H_))[tid];
    float s  = v.x + v.y + v.z + v.w;
    float ss = v.x*v.x + v.y*v.y + v.z*v.z + v.w*v.w;
    #pragma unroll
    for (int off = 16; off; off >>= 1) {
        s  += __shfl_down_sync(0xffffffffu, s,  off);
        ss += __shfl_down_sync(0xffffffffu, ss, off);
    }
    __shared__ float rs_[8], rss_[8];
    __shared__ float s_mu, s_rs;
    if ((tid & 31) == 0) { rs_[tid >> 5] = s; rss_[tid >> 5] = ss; }
    __syncthreads();
    if (tid == 0) {
        float S = 0.f, SS = 0.f;
        #pragma unroll
        for (int i = 0; i < 8; i++) { S += rs_[i]; SS += rss_[i]; }
        float mu  = S * (1.0f / H_);
        float var = SS * (1.0f / H_) - mu * mu;
        s_mu = mu; s_rs = rsqrtf(var + EPS_);
    }
    __syncthreads();
    const float mu = s_mu, rstd = s_rs;
    float4 g4 = ((const float4*)gamma)[tid];
    float4 b4 = ((const float4*)beta)[tid];
    float o0 = (v.x - mu) * rstd * g4.x + b4.x;
    float o1 = (v.y - mu) * rstd * g4.y + b4.y;
    float o2 = (v.z - mu) * rstd * g4.z + b4.z;
    float o3 = (v.w - mu) * rstd * g4.w + b4.w;
    __half2 p0 = __floats2half2_rn(o0, o1);
    __half2 p1 = __floats2half2_rn(o2, o3);
    uint2 pk = make_uint2(*(uint32_t*)&p0, *(uint32_t*)&p1);
    *(uint2*)(g_xh + (size_t)row * H_ + tid * 4) = pk;
}

// ---------------------------------------------------------------------------
// Kernel 2: W1 [K=1024][N=512] fp32 -> W1^T f16 [N][K]
// ---------------------------------------------------------------------------
__global__ void w1_transpose_kernel(const float* __restrict__ W1)
{
    __shared__ float tile[32][33];
    const int n0 = blockIdx.x * 32, k0 = blockIdx.y * 32;
    const int tx = threadIdx.x, ty = threadIdx.y;   // (32, 8)
    #pragma unroll
    for (int i = 0; i < 4; i++)
        tile[ty + 8*i][tx] = W1[(size_t)(k0 + ty + 8*i) * HD2 + n0 + tx];
    __syncthreads();
    #pragma unroll
    for (int i = 0; i < 4; i++)
        g_w1th[(size_t)(n0 + ty + 8*i) * H_ + k0 + tx] =
            __float2half(tile[tx][ty + 8*i]);
}

// ---------------------------------------------------------------------------
// Kernel 3: GEMM1 f16 mma.sync m16n8k16, f16 ACCUMULATE.
// CTA tile 128(M)x256(N), 256 threads (8 warps, 2Mx4N), warp tile 64x64,
// K-tile 32 halves, 3-stage cp.async, ldmatrix.x4. Per-warp code = R4/R6.
// ---------------------------------------------------------------------------
#define ROWB    80                       // 64B data + 16B pad
#define TILE_A  (128 * ROWB)             // 10240
#define TILE_BB (256 * ROWB)             // 20480
#define STG_B   (TILE_A + TILE_BB)       // 30720
#define NSTG    3
#define NKT     32                       // 1024 / 32
#define GEMM1_SMEM (NSTG * STG_B)        // 92160

__global__ void __launch_bounds__(256, 2) gemm1_tc_kernel(const float* __restrict__ b1)
{
    extern __shared__ __align__(16) char dsm[];
    const uint32_t sbase = (uint32_t)__cvta_generic_to_shared(dsm);

    const int tid  = threadIdx.x;
    const int m0   = blockIdx.y * 128;
    const int n0   = blockIdx.x * 256;
    const int warp = tid >> 5, lane = tid & 31;
    const int wm   = warp & 1;            // M half (64 rows)
    const int wn   = warp >> 1;           // N quarter (64 cols)

    uint32_t offA[4], offB[4];
    {
        const int rA = (lane & 15);
        const int cA = (lane >> 4);
        #pragma unroll
        for (int mt = 0; mt < 4; mt++)
            offA[mt] = (uint32_t)((wm * 64 + mt * 16 + rA) * ROWB + cA * 16);
        const int rB = (lane & 7) + ((lane >> 4) << 3);
        const int cB = (lane >> 3) & 1;
        #pragma unroll
        for (int p = 0; p < 4; p++)
            offB[p] = (uint32_t)(TILE_A + (wn * 64 + p * 16 + rB) * ROWB + cB * 16);
    }

    // loaders: A -> 2 threads/row (2x16B each), B -> 1 thread/row (4x16B)
    const int aRow = tid >> 1;
    const int aHalf = tid & 1;            // 32B half of the 64B row
    const __half* Ag = g_xh   + (size_t)(m0 + aRow) * H_ + aHalf * 16;
    const __half* Bg = g_w1th + (size_t)(n0 + tid) * H_;
    const uint32_t dA = sbase + aRow * ROWB + aHalf * 32;
    const uint32_t dB = sbase + TILE_A + tid * ROWB;

    uint32_t acc[4][8][2];                 // f16x2 accumulators
    #pragma unroll
    for (int mt = 0; mt < 4; mt++)
        #pragma unroll
        for (int nt = 0; nt < 8; nt++) { acc[mt][nt][0] = 0u; acc[mt][nt][1] = 0u; }

    #pragma unroll
    for (int p = 0; p < 2; ++p) {
        const uint32_t sg = p * STG_B;
        cp16s(dA + sg,      Ag + p * 32);
        cp16s(dA + sg + 16, Ag + p * 32 + 8);
        #pragma unroll
        for (int c = 0; c < 4; c++)
            cp16s(dB + sg + c * 16, Bg + p * 32 + c * 8);
        asm volatile("cp.async.commit_group;");
    }

    for (int t = 0; t < NKT; ++t) {
        if (t < NKT - 1) asm volatile("cp.async.wait_group 1;");
        else             asm volatile("cp.async.wait_group 0;");
        __syncthreads();

        const uint32_t sS = sbase + (t % NSTG) * STG_B;
        #pragma unroll
        for (int kt = 0; kt < 2; ++kt) {
            uint32_t a[4][4], b[4][4];
            #pragma unroll
            for (int mt = 0; mt < 4; mt++) ldsm4(a[mt], sS + offA[mt] + kt * 32);
            #pragma unroll
            for (int p = 0; p < 4; p++)    ldsm4(b[p],  sS + offB[p]  + kt * 32);
            #pragma unroll
            for (int mt = 0; mt < 4; mt++)
                #pragma unroll
                for (int nt = 0; nt < 8; nt++) {
                    const uint32_t b0  = b[nt >> 1][(nt & 1) * 2];
                    const uint32_t b1r = b[nt >> 1][(nt & 1) * 2 + 1];
                    asm volatile(
                        "mma.sync.aligned.m16n8k16.row.col.f16.f16.f16.f16 "
                        "{%0,%1},{%2,%3,%4,%5},{%6,%7},{%0,%1};"
                        : "+r"(acc[mt][nt][0]), "+r"(acc[mt][nt][1])
                        : "r"(a[mt][0]), "r"(a[mt][1]), "r"(a[mt][2]), "r"(a[mt][3]),
                          "r"(b0), "r"(b1r));
                }
        }

        if (t + 2 < NKT) {
            const uint32_t sg = ((t + 2) % NSTG) * STG_B;
            const int k0 = (t + 2) * 32;
            cp16s(dA + sg,      Ag + k0);
            cp16s(dA + sg + 16, Ag + k0 + 8);
            #pragma unroll
            for (int c = 0; c < 4; c++)
                cp16s(dB + sg + c * 16, Bg + k0 + c * 8);
            asm volatile("cp.async.commit_group;");
        }
    }

    // epilogue: +b1, exact GELU, bf16 store
    const int r = lane >> 2, tig = lane & 3;
    #pragma unroll
    for (int nt = 0; nt < 8; nt++) {
        const int col = n0 + wn * 64 + nt * 8 + 2 * tig;
        const float bx = __ldg(b1 + col), by = __ldg(b1 + col + 1);
        #pragma unroll
        for (int mt = 0; mt < 4; mt++) {
            const int row = m0 + wm * 64 + mt * 16 + r;
            float2 f01 = __half22float2(*(__half2*)&acc[mt][nt][0]);
            float2 f23 = __half22float2(*(__half2*)&acc[mt][nt][1]);
            float c0 = f01.x + bx, c1 = f01.y + by;
            float c2 = f23.x + bx, c3 = f23.y + by;
            c0 = 0.5f * c0 * (1.0f + erff(c0 * 0.70710678118654752f));
            c1 = 0.5f * c1 * (1.0f + erff(c1 * 0.70710678118654752f));
            c2 = 0.5f * c2 * (1.0f + erff(c2 * 0.70710678118654752f));
            c3 = 0.5f * c3 * (1.0f + erff(c3 * 0.70710678118654752f));
            *(__nv_bfloat162*)(g_hb + (size_t)row * HD2 + col)       = __floats2bfloat162_rn(c0, c1);
            *(__nv_bfloat162*)(g_hb + (size_t)(row + 8) * HD2 + col) = __floats2bfloat162_rn(c2, c3);
        }
    }
}

// ---------------------------------------------------------------------------
// Kernel 4: GEMM2 split-K2, 64 tokens / 128-thread block, grid 512.
// ---------------------------------------------------------------------------
__global__ void __launch_bounds__(128) gemm2_kernel(
    const float* __restrict__ W2, const float* __restrict__ b2)
{
    __shared__ float w2s[HD2 * 12];   // 24 KB, row k -> 12 floats (9 used)
    __shared__ float b2s[L_];
    for (int i = threadIdx.x; i < HD2 * L_; i += 128)
        w2s[(i / L_) * 12 + (i % L_)] = W2[i];
    if (threadIdx.x < L_) b2s[threadIdx.x] = b2[threadIdx.x];
    __syncthreads();

    const int warp = threadIdx.x >> 5;
    const int lane = threadIdx.x & 31;
    const int half = lane >> 4;
    const int tok  = blockIdx.x * 64 + warp * 16 + (lane & 15);

    const uint4* hp = (const uint4*)(g_hb + (size_t)tok * HD2 + half * 256);
    const float* wbase = &w2s[(half * 256) * 12];

    float acc[L_];
    #pragma unroll
    for (int l = 0; l < L_; l++) acc[l] = 0.f;

    #pragma unroll 8
    for (int c = 0; c < 32; ++c) {
        uint4 v = hp[c];
        float h[8];
        h[0] = __uint_as_float(v.x << 16); h[1] = __uint_as_float(v.x & 0xffff0000u);
        h[2] = __uint_as_float(v.y << 16); h[3] = __uint_as_float(v.y & 0xffff0000u);
        h[4] = __uint_as_float(v.z << 16); h[5] = __uint_as_float(v.z & 0xffff0000u);
        h[6] = __uint_as_float(v.w << 16); h[7] = __uint_as_float(v.w & 0xffff0000u);
        #pragma unroll
        for (int j = 0; j < 8; j++) {
            const float* w = wbase + (c * 8 + j) * 12;
            float4 w0 = *(const float4*)(w);
            float4 w1 = *(const float4*)(w + 4);
            float  w8 = w[8];
            acc[0] = fmaf(h[j], w0.x, acc[0]);
            acc[1] = fmaf(h[j], w0.y, acc[1]);
            acc[2] = fmaf(h[j], w0.z, acc[2]);
            acc[3] = fmaf(h[j], w0.w, acc[3]);
            acc[4] = fmaf(h[j], w1.x, acc[4]);
            acc[5] = fmaf(h[j], w1.y, acc[5]);
            acc[6] = fmaf(h[j], w1.z, acc[6]);
            acc[7] = fmaf(h[j], w1.w, acc[7]);
            acc[8] = fmaf(h[j], w8,   acc[8]);
        }
    }
    #pragma unroll
    for (int l = 0; l < L_; l++)
        acc[l] += __shfl_down_sync(0xffffffffu, acc[l], 16);
    if (half == 0) {
        float* out = g_em + (size_t)tok * L_;
        #pragma unroll
        for (int l = 0; l < L_; l++) out[l] = acc[l] + b2s[l];
    }
}

// ---------------------------------------------------------------------------
// Kernel 5: CRF. Ballot-precomputed masks; em loads double-buffered 8 ahead.
// ---------------------------------------------------------------------------
__global__ void crf_kernel(const float* __restrict__ st,
                           const float* __restrict__ et,
                           const float* __restrict__ trans,
                           const int*   __restrict__ labels,
                           const int*   __restrict__ am)
{
    const int b    = blockIdx.x;
    const int lane = threadIdx.x;
    const float* em  = g_em + (size_t)b * S_ * L_;
    const int*   lab = labels + (size_t)b * S_;
    const int*   amk = am     + (size_t)b * S_;

    // ---- warp-uniform mask words ----
    uint32_t mword[16];
    #pragma unroll
    for (int c = 0; c < 16; c++) {
        int t = c * 32 + lane;
        int l = lab[t];
        bool mk = (l != -100) && (amk[t] == 1);
        mword[c] = __ballot_sync(0xffffffffu, mk);
    }

    // ---- numerator ----
    float part = 0.f;
    int   cnt  = 0;
    for (int t = lane; t < S_; t += 32) {
        bool rw = (mword[t >> 5] >> (t & 31)) & 1;
        bool mk = (t == 0) ? true : rw;
        if (mk) cnt++;
        if (t > 0 && rw) {
            int tp = lab[t - 1]; if (tp == -100) tp = 0;
            int tc = lab[t];     if (tc == -100) tc = 0;
            part += trans[tp * L_ + tc] + em[t * L_ + tc];
        }
    }
    #pragma unroll
    for (int off = 16; off; off >>= 1) {
        part += __shfl_down_sync(0xffffffffu, part, off);
        cnt  += __shfl_down_sync(0xffffffffu, cnt,  off);
    }
    float num = 0.f;
    if (lane == 0) {
        int tg0 = lab[0]; if (tg0 == -100) tg0 = 0;
        num = part + st[tg0] + em[tg0];
        int se = cnt - 1;
        int lt = lab[se]; if (lt == -100) lt = 0;
        num += et[lt];
    }

    // ---- denominator: linear-space scan, deep em prefetch ----
    const int j = lane;
    float c_[L_];
    #pragma unroll
    for (int i = 0; i < L_; i++)
        c_[i] = (j < L_) ? ex2f_(trans[i * L_ + j] * LOG2E_) : 0.f;

    float p  = (j < L_) ? ex2f_((st[j] + em[j]) * LOG2E_) : 0.f;
    float C2 = 0.f;

    float cur[8], nxt[8];
    #pragma unroll
    for (int i = 0; i < 8; i++)
        cur[i] = (j < L_) ? em[(1 + i) * L_ + j] : 0.f;

    for (int tb = 1; tb < S_; tb += 8) {
        #pragma unroll
        for (int i = 0; i < 8; i++) {
            int tn = tb + 8 + i;
            nxt[i] = (tn < S_ && j < L_) ? em[tn * L_ + j] : 0.f;
        }
        {
            float m = __shfl_sync(0xffffffffu, p, 0);
            int e = (__float_as_int(m) >> 23) & 255;
            float sc = __int_as_float((254 - e) << 23);
            p *= sc;
            C2 += (float)(e - 127);
        }
        #pragma unroll
        for (int i = 0; i < 8; i++) {
            int t = tb + i;
            if (t < S_) {
                float eem = ex2f_(cur[i] * LOG2E_);
                float pa[L_];
                #pragma unroll
                for (int q = 0; q < L_; q++) pa[q] = __shfl_sync(0xffffffffu, p, q);
                float s01 = fmaf(pa[1], c_[1], pa[0] * c_[0]);
                float s23 = fmaf(pa[3], c_[3], pa[2] * c_[2]);
                float s45 = fmaf(pa[5], c_[5], pa[4] * c_[4]);
                float s67 = fmaf(pa[7], c_[7], pa[6] * c_[6]);
                float s8  = pa[8] * c_[8];
                float s   = (s01 + s23) + (s45 + s67) + s8;
                float pn  = s * eem;
                bool mk = (mword[t >> 5] >> (t & 31)) & 1;
                p = mk ? pn : p;
            }
        }
        #pragma unroll
        for (int i = 0; i < 8; i++) cur[i] = nxt[i];
    }

    float fv = (j < L_) ? p * ex2f_(et[j] * LOG2E_) : 0.f;
    #pragma unroll
    for (int off = 16; off; off >>= 1) fv += __shfl_xor_sync(0xffffffffu, fv, off);
    float denom = (C2 + lg2f_(fv)) * LN2_;

    if (lane == 0) g_llh[b] = num - denom;
}

// ---------------------------------------------------------------------------
__global__ void finalize_kernel(float* __restrict__ out) {
    int t = threadIdx.x;                     // 64
    float v = g_llh[t];
    #pragma unroll
    for (int off = 16; off; off >>= 1) v += __shfl_down_sync(0xffffffffu, v, off);
    __shared__ float r[2];
    if ((t & 31) == 0) r[t >> 5] = v;
    __syncthreads();
    if (t == 0) out[0] = -((r[0] + r[1]) * (1.0f / B_));
}

// ---------------------------------------------------------------------------
extern "C" void kernel_launch(void* const* d_in, const int* in_sizes, int n_in,
                              void* d_out, int out_size)
{
    const float* hs    = (const float*)d_in[0];
    const float* gamma = (const float*)d_in[1];
    const float* beta  = (const float*)d_in[2];
    const float* W1    = (const float*)d_in[3];
    const float* b1    = (const float*)d_in[4];
    const float* W2    = (const float*)d_in[5];
    const float* b2    = (const float*)d_in[6];
    const float* st    = (const float*)d_in[7];
    const float* et    = (const float*)d_in[8];
    const float* trans = (const float*)d_in[9];
    const int*   labels= (const int*)d_in[10];
    const int*   am    = (const int*)d_in[11];

    cudaFuncSetAttribute(gemm1_tc_kernel,
                         cudaFuncAttributeMaxDynamicSharedMemorySize, GEMM1_SMEM);

    ln_norm_kernel<<<NTOK, 256>>>(hs, gamma, beta);
    w1_transpose_kernel<<<dim3(HD2 / 32, H_ / 32), dim3(32, 8)>>>(W1);
    marker_kernel<<<1, 32>>>();
    gemm1_tc_kernel<<<dim3(HD2 / 256, NTOK / 128), 256, GEMM1_SMEM>>>(b1);
    gemm2_kernel<<<NTOK / 64, 128>>>(W2, b2);
    crf_kernel<<<B_, 32>>>(st, et, trans, labels, am);
    finalize_kernel<<<1, 64>>>((float*)d_out);
}

// round 8
// speedup vs baseline: 1.3093x; 1.0050x over previous
#include <cuda_runtime.h>
#include <cuda_bf16.h>
#include <cuda_fp16.h>
#include <cuda_fp8.h>
#include <math.h>
#include <stdint.h>

#define B_    64
#define S_    512
#define H_    1024
#define HD2   512
#define L_    9
#define NTOK  (B_*S_)
#define EPS_  1e-5f
#define LOG2E_ 1.4426950408889634f
#define LN2_   0.6931471805599453f
#define W1SCL  64.0f
#define W1INV  0.015625f

// ---------------- device scratch (no allocation allowed) -------------------
__device__ uint8_t g_x8[(size_t)NTOK * H_];          // LN-normalized X, e4m3
__device__ uint8_t g_w1t8[(size_t)HD2 * H_];         // (W1*64)^T e4m3 [N][K]
__device__ __nv_bfloat16 g_hb[(size_t)NTOK * HD2];   // post-GELU h, bf16
__device__ float g_em[(size_t)NTOK * L_];            // emissions fp32
__device__ float g_llh[B_];

// ---------------------------------------------------------------------------
__device__ __forceinline__ float ex2f_(float x){ float y; asm("ex2.approx.ftz.f32 %0,%1;":"=f"(y):"f"(x)); return y; }
__device__ __forceinline__ float lg2f_(float x){ float y; asm("lg2.approx.ftz.f32 %0,%1;":"=f"(y):"f"(x)); return y; }

__device__ __forceinline__ void cp16s(uint32_t dst, const void* src){
    asm volatile("cp.async.cg.shared.global [%0], [%1], 16;" :: "r"(dst), "l"(src));
}
__device__ __forceinline__ void ldsm4(uint32_t* r, uint32_t addr){
    asm volatile("ldmatrix.sync.aligned.m8n8.x4.shared.b16 {%0,%1,%2,%3}, [%4];"
        : "=r"(r[0]), "=r"(r[1]), "=r"(r[2]), "=r"(r[3]) : "r"(addr));
}
__device__ __forceinline__ uint16_t f2e4m3x2_(float hi, float lo){
    uint16_t r;
    asm("cvt.rn.satfinite.e4m3x2.f32 %0, %1, %2;" : "=h"(r) : "f"(hi), "f"(lo));
    return r;
}

// ---------------------------------------------------------------------------
// no-op marker: keeps the launch sequence aligned so ncu captures gemm1
// ---------------------------------------------------------------------------
__global__ void marker_kernel() {}

// ---------------------------------------------------------------------------
// Kernel 1: LayerNorm -> normalized e4m3 X
// ---------------------------------------------------------------------------
__global__ void ln_norm_kernel(const float* __restrict__ hs,
                               const float* __restrict__ gamma,
                               const float* __restrict__ beta)
{
    const int row = blockIdx.x;
    const int tid = threadIdx.x;                      // 256
    float4 v = ((const float4*)(hs + (size_t)row * H_))[tid];
    float s  = v.x + v.y + v.z + v.w;
    float ss = v.x*v.x + v.y*v.y + v.z*v.z + v.w*v.w;
    #pragma unroll
    for (int off = 16; off; off >>= 1) {
        s  += __shfl_down_sync(0xffffffffu, s,  off);
        ss += __shfl_down_sync(0xffffffffu, ss, off);
    }
    __shared__ float rs_[8], rss_[8];
    __shared__ float s_mu, s_rs;
    if ((tid & 31) == 0) { rs_[tid >> 5] = s; rss_[tid >> 5] = ss; }
    __syncthreads();
    if (tid == 0) {
        float S = 0.f, SS = 0.f;
        #pragma unroll
        for (int i = 0; i < 8; i++) { S += rs_[i]; SS += rss_[i]; }
        float mu  = S * (1.0f / H_);
        float var = SS * (1.0f / H_) - mu * mu;
        s_mu = mu; s_rs = rsqrtf(var + EPS_);
    }
    __syncthreads();
    const float mu = s_mu, rstd = s_rs;
    float4 g4 = ((const float4*)gamma)[tid];
    float4 b4 = ((const float4*)beta)[tid];
    float o0 = (v.x - mu) * rstd * g4.x + b4.x;
    float o1 = (v.y - mu) * rstd * g4.y + b4.y;
    float o2 = (v.z - mu) * rstd * g4.z + b4.z;
    float o3 = (v.w - mu) * rstd * g4.w + b4.w;
    uint32_t lo = f2e4m3x2_(o1, o0);
    uint32_t hi = f2e4m3x2_(o3, o2);
    *(uint32_t*)(g_x8 + (size_t)row * H_ + tid * 4) = lo | (hi << 16);
}

// ---------------------------------------------------------------------------
// Kernel 2: W1 [K=1024][N=512] fp32 -> (W1*64)^T e4m3 [N][K]
// ---------------------------------------------------------------------------
__global__ void w1_transpose_kernel(const float* __restrict__ W1)
{
    __shared__ float tile[32][33];
    const int n0 = blockIdx.x * 32, k0 = blockIdx.y * 32;
    const int tx = threadIdx.x, ty = threadIdx.y;   // (32, 8)
    #pragma unroll
    for (int i = 0; i < 4; i++)
        tile[ty + 8*i][tx] = W1[(size_t)(k0 + ty + 8*i) * HD2 + n0 + tx];
    __syncthreads();
    #pragma unroll
    for (int i = 0; i < 4; i++) {
        uint16_t p = f2e4m3x2_(0.f, tile[tx][ty + 8*i] * W1SCL);
        g_w1t8[(size_t)(n0 + ty + 8*i) * H_ + k0 + tx] = (uint8_t)(p & 0xff);
    }
}

// ---------------------------------------------------------------------------
// Kernel 3: GEMM1 e4m3 mma.sync m16n8k32 with f16 ACCUMULATE.
// CTA tile 128(M)x256(N), 256 threads (8 warps 2Mx4N), warp tile 64x64,
// K-tile = 64 bytes, 3-stage cp.async, ldmatrix.x4.
// Byte layout identical to verified R5 (fp8) / R7 (tiling).
// ---------------------------------------------------------------------------
#define ROWB    80                       // 64B data + 16B pad
#define TILE_A  (128 * ROWB)             // 10240
#define TILE_BB (256 * ROWB)             // 20480
#define STG_B   (TILE_A + TILE_BB)       // 30720
#define NSTG    3
#define NKT     16                       // 1024B / 64B
#define GEMM1_SMEM (NSTG * STG_B)        // 92160

__global__ void __launch_bounds__(256, 2) gemm1_tc_kernel(const float* __restrict__ b1)
{
    extern __shared__ __align__(16) char dsm[];
    const uint32_t sbase = (uint32_t)__cvta_generic_to_shared(dsm);

    const int tid  = threadIdx.x;
    const int m0   = blockIdx.y * 128;
    const int n0   = blockIdx.x * 256;
    const int warp = tid >> 5, lane = tid & 31;
    const int wm   = warp & 1;            // M half (64 rows)
    const int wn   = warp >> 1;           // N quarter (64 cols)

    uint32_t offA[4], offB[4];
    {
        const int rA = (lane & 15);
        const int cA = (lane >> 4);
        #pragma unroll
        for (int mt = 0; mt < 4; mt++)
            offA[mt] = (uint32_t)((wm * 64 + mt * 16 + rA) * ROWB + cA * 16);
        const int rB = (lane & 7) + ((lane >> 4) << 3);
        const int cB = (lane >> 3) & 1;
        #pragma unroll
        for (int p = 0; p < 4; p++)
            offB[p] = (uint32_t)(TILE_A + (wn * 64 + p * 16 + rB) * ROWB + cB * 16);
    }

    // loaders: A -> 2 threads/row (2x16B each), B -> 1 thread/row (4x16B)
    const int aRow  = tid >> 1;
    const int aHalf = tid & 1;            // 32B half of the 64B row
    const uint8_t* Ag = g_x8   + (size_t)(m0 + aRow) * H_ + aHalf * 32;
    const uint8_t* Bg = g_w1t8 + (size_t)(n0 + tid) * H_;
    const uint32_t dA = sbase + aRow * ROWB + aHalf * 32;
    const uint32_t dB = sbase + TILE_A + tid * ROWB;

    uint32_t acc[4][8][2];                 // f16x2 accumulators
    #pragma unroll
    for (int mt = 0; mt < 4; mt++)
        #pragma unroll
        for (int nt = 0; nt < 8; nt++) { acc[mt][nt][0] = 0u; acc[mt][nt][1] = 0u; }

    #pragma unroll
    for (int p = 0; p < 2; ++p) {
        const uint32_t sg = p * STG_B;
        cp16s(dA + sg,      Ag + p * 64);
        cp16s(dA + sg + 16, Ag + p * 64 + 16);
        #pragma unroll
        for (int c = 0; c < 4; c++)
            cp16s(dB + sg + c * 16, Bg + p * 64 + c * 16);
        asm volatile("cp.async.commit_group;");
    }

    for (int t = 0; t < NKT; ++t) {
        if (t < NKT - 1) asm volatile("cp.async.wait_group 1;");
        else             asm volatile("cp.async.wait_group 0;");
        __syncthreads();

        const uint32_t sS = sbase + (t % NSTG) * STG_B;
        #pragma unroll
        for (int kt = 0; kt < 2; ++kt) {            // two k32 steps per 64B row
            uint32_t a[4][4], b[4][4];
            #pragma unroll
            for (int mt = 0; mt < 4; mt++) ldsm4(a[mt], sS + offA[mt] + kt * 32);
            #pragma unroll
            for (int p = 0; p < 4; p++)    ldsm4(b[p],  sS + offB[p]  + kt * 32);
            #pragma unroll
            for (int mt = 0; mt < 4; mt++)
                #pragma unroll
                for (int nt = 0; nt < 8; nt++) {
                    const uint32_t b0  = b[nt >> 1][(nt & 1) * 2];
                    const uint32_t b1r = b[nt >> 1][(nt & 1) * 2 + 1];
                    asm volatile(
                        "mma.sync.aligned.m16n8k32.row.col.f16.e4m3.e4m3.f16 "
                        "{%0,%1},{%2,%3,%4,%5},{%6,%7},{%0,%1};"
                        : "+r"(acc[mt][nt][0]), "+r"(acc[mt][nt][1])
                        : "r"(a[mt][0]), "r"(a[mt][1]), "r"(a[mt][2]), "r"(a[mt][3]),
                          "r"(b0), "r"(b1r));
                }
        }

        if (t + 2 < NKT) {
            const uint32_t sg = ((t + 2) % NSTG) * STG_B;
            const int k0 = (t + 2) * 64;
            cp16s(dA + sg,      Ag + k0);
            cp16s(dA + sg + 16, Ag + k0 + 16);
            #pragma unroll
            for (int c = 0; c < 4; c++)
                cp16s(dB + sg + c * 16, Bg + k0 + c * 16);
            asm volatile("cp.async.commit_group;");
        }
    }

    // epilogue: /64, +b1, exact GELU, bf16 store
    const int r = lane >> 2, tig = lane & 3;
    #pragma unroll
    for (int nt = 0; nt < 8; nt++) {
        const int col = n0 + wn * 64 + nt * 8 + 2 * tig;
        const float bx = __ldg(b1 + col), by = __ldg(b1 + col + 1);
        #pragma unroll
        for (int mt = 0; mt < 4; mt++) {
            const int row = m0 + wm * 64 + mt * 16 + r;
            float2 f01 = __half22float2(*(__half2*)&acc[mt][nt][0]);
            float2 f23 = __half22float2(*(__half2*)&acc[mt][nt][1]);
            float c0 = f01.x * W1INV + bx, c1 = f01.y * W1INV + by;
            float c2 = f23.x * W1INV + bx, c3 = f23.y * W1INV + by;
            c0 = 0.5f * c0 * (1.0f + erff(c0 * 0.70710678118654752f));
            c1 = 0.5f * c1 * (1.0f + erff(c1 * 0.70710678118654752f));
            c2 = 0.5f * c2 * (1.0f + erff(c2 * 0.70710678118654752f));
            c3 = 0.5f * c3 * (1.0f + erff(c3 * 0.70710678118654752f));
            *(__nv_bfloat162*)(g_hb + (size_t)row * HD2 + col)       = __floats2bfloat162_rn(c0, c1);
            *(__nv_bfloat162*)(g_hb + (size_t)(row + 8) * HD2 + col) = __floats2bfloat162_rn(c2, c3);
        }
    }
}

// ---------------------------------------------------------------------------
// Kernel 4: GEMM2 split-K2, 64 tokens / 128-thread block, grid 512.
// ---------------------------------------------------------------------------
__global__ void __launch_bounds__(128) gemm2_kernel(
    const float* __restrict__ W2, const float* __restrict__ b2)
{
    __shared__ float w2s[HD2 * 12];   // 24 KB, row k -> 12 floats (9 used)
    __shared__ float b2s[L_];
    for (int i = threadIdx.x; i < HD2 * L_; i += 128)
        w2s[(i / L_) * 12 + (i % L_)] = W2[i];
    if (threadIdx.x < L_) b2s[threadIdx.x] = b2[threadIdx.x];
    __syncthreads();

    const int warp = threadIdx.x >> 5;
    const int lane = threadIdx.x & 31;
    const int half = lane >> 4;
    const int tok  = blockIdx.x * 64 + warp * 16 + (lane & 15);

    const uint4* hp = (const uint4*)(g_hb + (size_t)tok * HD2 + half * 256);
    const float* wbase = &w2s[(half * 256) * 12];

    float acc[L_];
    #pragma unroll
    for (int l = 0; l < L_; l++) acc[l] = 0.f;

    #pragma unroll 8
    for (int c = 0; c < 32; ++c) {
        uint4 v = hp[c];
        float h[8];
        h[0] = __uint_as_float(v.x << 16); h[1] = __uint_as_float(v.x & 0xffff0000u);
        h[2] = __uint_as_float(v.y << 16); h[3] = __uint_as_float(v.y & 0xffff0000u);
        h[4] = __uint_as_float(v.z << 16); h[5] = __uint_as_float(v.z & 0xffff0000u);
        h[6] = __uint_as_float(v.w << 16); h[7] = __uint_as_float(v.w & 0xffff0000u);
        #pragma unroll
        for (int j = 0; j < 8; j++) {
            const float* w = wbase + (c * 8 + j) * 12;
            float4 w0 = *(const float4*)(w);
            float4 w1 = *(const float4*)(w + 4);
            float  w8 = w[8];
            acc[0] = fmaf(h[j], w0.x, acc[0]);
            acc[1] = fmaf(h[j], w0.y, acc[1]);
            acc[2] = fmaf(h[j], w0.z, acc[2]);
            acc[3] = fmaf(h[j], w0.w, acc[3]);
            acc[4] = fmaf(h[j], w1.x, acc[4]);
            acc[5] = fmaf(h[j], w1.y, acc[5]);
            acc[6] = fmaf(h[j], w1.z, acc[6]);
            acc[7] = fmaf(h[j], w1.w, acc[7]);
            acc[8] = fmaf(h[j], w8,   acc[8]);
        }
    }
    #pragma unroll
    for (int l = 0; l < L_; l++)
        acc[l] += __shfl_down_sync(0xffffffffu, acc[l], 16);
    if (half == 0) {
        float* out = g_em + (size_t)tok * L_;
        #pragma unroll
        for (int l = 0; l < L_; l++) out[l] = acc[l] + b2s[l];
    }
}

// ---------------------------------------------------------------------------
// Kernel 5: CRF. Ballot masks; linear-space scan; deep em prefetch.
// ---------------------------------------------------------------------------
__global__ void crf_kernel(const float* __restrict__ st,
                           const float* __restrict__ et,
                           const float* __restrict__ trans,
                           const int*   __restrict__ labels,
                           const int*   __restrict__ am)
{
    const int b    = blockIdx.x;
    const int lane = threadIdx.x;
    const float* em  = g_em + (size_t)b * S_ * L_;
    const int*   lab = labels + (size_t)b * S_;
    const int*   amk = am     + (size_t)b * S_;

    uint32_t mword[16];
    #pragma unroll
    for (int c = 0; c < 16; c++) {
        int t = c * 32 + lane;
        int l = lab[t];
        bool mk = (l != -100) && (amk[t] == 1);
        mword[c] = __ballot_sync(0xffffffffu, mk);
    }

    float part = 0.f;
    int   cnt  = 0;
    for (int t = lane; t < S_; t += 32) {
        bool rw = (mword[t >> 5] >> (t & 31)) & 1;
        bool mk = (t == 0) ? true : rw;
        if (mk) cnt++;
        if (t > 0 && rw) {
            int tp = lab[t - 1]; if (tp == -100) tp = 0;
            int tc = lab[t];     if (tc == -100) tc = 0;
            part += trans[tp * L_ + tc] + em[t * L_ + tc];
        }
    }
    #pragma unroll
    for (int off = 16; off; off >>= 1) {
        part += __shfl_down_sync(0xffffffffu, part, off);
        cnt  += __shfl_down_sync(0xffffffffu, cnt,  off);
    }
    float num = 0.f;
    if (lane == 0) {
        int tg0 = lab[0]; if (tg0 == -100) tg0 = 0;
        num = part + st[tg0] + em[tg0];
        int se = cnt - 1;
        int lt = lab[se]; if (lt == -100) lt = 0;
        num += et[lt];
    }

    const int j = lane;
    float c_[L_];
    #pragma unroll
    for (int i = 0; i < L_; i++)
        c_[i] = (j < L_) ? ex2f_(trans[i * L_ + j] * LOG2E_) : 0.f;

    float p  = (j < L_) ? ex2f_((st[j] + em[j]) * LOG2E_) : 0.f;
    float C2 = 0.f;

    float cur[8], nxt[8];
    #pragma unroll
    for (int i = 0; i < 8; i++)
        cur[i] = (j < L_) ? em[(1 + i) * L_ + j] : 0.f;

    for (int tb = 1; tb < S_; tb += 8) {
        #pragma unroll
        for (int i = 0; i < 8; i++) {
            int tn = tb + 8 + i;
            nxt[i] = (tn < S_ && j < L_) ? em[tn * L_ + j] : 0.f;
        }
        {
            float m = __shfl_sync(0xffffffffu, p, 0);
            int e = (__float_as_int(m) >> 23) & 255;
            float sc = __int_as_float((254 - e) << 23);
            p *= sc;
            C2 += (float)(e - 127);
        }
        #pragma unroll
        for (int i = 0; i < 8; i++) {
            int t = tb + i;
            if (t < S_) {
                float eem = ex2f_(cur[i] * LOG2E_);
                float pa[L_];
                #pragma unroll
                for (int q = 0; q < L_; q++) pa[q] = __shfl_sync(0xffffffffu, p, q);
                float s01 = fmaf(pa[1], c_[1], pa[0] * c_[0]);
                float s23 = fmaf(pa[3], c_[3], pa[2] * c_[2]);
                float s45 = fmaf(pa[5], c_[5], pa[4] * c_[4]);
                float s67 = fmaf(pa[7], c_[7], pa[6] * c_[6]);
                float s8  = pa[8] * c_[8];
                float s   = (s01 + s23) + (s45 + s67) + s8;
                float pn  = s * eem;
                bool mk = (mword[t >> 5] >> (t & 31)) & 1;
                p = mk ? pn : p;
            }
        }
        #pragma unroll
        for (int i = 0; i < 8; i++) cur[i] = nxt[i];
    }

    float fv = (j < L_) ? p * ex2f_(et[j] * LOG2E_) : 0.f;
    #pragma unroll
    for (int off = 16; off; off >>= 1) fv += __shfl_xor_sync(0xffffffffu, fv, off);
    float denom = (C2 + lg2f_(fv)) * LN2_;

    if (lane == 0) g_llh[b] = num - denom;
}

// ---------------------------------------------------------------------------
__global__ void finalize_kernel(float* __restrict__ out) {
    int t = threadIdx.x;                     // 64
    float v = g_llh[t];
    #pragma unroll
    for (int off = 16; off; off >>= 1) v += __shfl_down_sync(0xffffffffu, v, off);
    __shared__ float r[2];
    if ((t & 31) == 0) r[t >> 5] = v;
    __syncthreads();
    if (t == 0) out[0] = -((r[0] + r[1]) * (1.0f / B_));
}

// ---------------------------------------------------------------------------
extern "C" void kernel_launch(void* const* d_in, const int* in_sizes, int n_in,
                              void* d_out, int out_size)
{
    const float* hs    = (const float*)d_in[0];
    const float* gamma = (const float*)d_in[1];
    const float* beta  = (const float*)d_in[2];
    const float* W1    = (const float*)d_in[3];
    const float* b1    = (const float*)d_in[4];
    const float* W2    = (const float*)d_in[5];
    const float* b2    = (const float*)d_in[6];
    const float* st    = (const float*)d_in[7];
    const float* et    = (const float*)d_in[8];
    const float* trans = (const float*)d_in[9];
    const int*   labels= (const int*)d_in[10];
    const int*   am    = (const int*)d_in[11];

    cudaFuncSetAttribute(gemm1_tc_kernel,
                         cudaFuncAttributeMaxDynamicSharedMemorySize, GEMM1_SMEM);

    ln_norm_kernel<<<NTOK, 256>>>(hs, gamma, beta);
    w1_transpose_kernel<<<dim3(HD2 / 32, H_ / 32), dim3(32, 8)>>>(W1);
    marker_kernel<<<1, 32>>>();
    gemm1_tc_kernel<<<dim3(HD2 / 256, NTOK / 128), 256, GEMM1_SMEM>>>(b1);
    gemm2_kernel<<<NTOK / 64, 128>>>(W2, b2);
    crf_kernel<<<B_, 32>>>(st, et, trans, labels, am);
    finalize_kernel<<<1, 64>>>((float*)d_out);
}

// round 9
// speedup vs baseline: 1.3458x; 1.0279x over previous
#include <cuda_runtime.h>
#include <cuda_bf16.h>
#include <cuda_fp16.h>
#include <cuda_fp8.h>
#include <math.h>
#include <stdint.h>

#define B_    64
#define S_    512
#define H_    1024
#define HD2   512
#define L_    9
#define NTOK  (B_*S_)
#define EPS_  1e-5f
#define LOG2E_ 1.4426950408889634f
#define LN2_   0.6931471805599453f
#define W1SCL  64.0f
#define W1INV  0.015625f

// ---------------- device scratch (no allocation allowed) -------------------
__device__ uint8_t g_x8[(size_t)NTOK * H_];          // LN-normalized X, e4m3
__device__ uint8_t g_w1t8[(size_t)HD2 * H_];         // (W1*64)^T e4m3 [N][K]
__device__ __nv_bfloat16 g_hb[(size_t)NTOK * HD2];   // post-GELU h, bf16
__device__ float g_em[(size_t)NTOK * L_];            // emissions fp32
__device__ float g_llh[B_];

// ---------------------------------------------------------------------------
__device__ __forceinline__ float ex2f_(float x){ float y; asm("ex2.approx.ftz.f32 %0,%1;":"=f"(y):"f"(x)); return y; }
__device__ __forceinline__ float lg2f_(float x){ float y; asm("lg2.approx.ftz.f32 %0,%1;":"=f"(y):"f"(x)); return y; }

__device__ __forceinline__ void cp16s(uint32_t dst, const void* src){
    asm volatile("cp.async.cg.shared.global [%0], [%1], 16;" :: "r"(dst), "l"(src));
}
__device__ __forceinline__ void ldsm4(uint32_t* r, uint32_t addr){
    asm volatile("ldmatrix.sync.aligned.m8n8.x4.shared.b16 {%0,%1,%2,%3}, [%4];"
        : "=r"(r[0]), "=r"(r[1]), "=r"(r[2]), "=r"(r[3]) : "r"(addr));
}
__device__ __forceinline__ uint16_t f2e4m3x2_(float hi, float lo){
    uint16_t r;
    asm("cvt.rn.satfinite.e4m3x2.f32 %0, %1, %2;" : "=h"(r) : "f"(hi), "f"(lo));
    return r;
}

// ---------------------------------------------------------------------------
// no-op marker: keeps the launch sequence aligned so ncu captures gemm1
// ---------------------------------------------------------------------------
__global__ void marker_kernel() {}

// ---------------------------------------------------------------------------
// Kernel 1: LayerNorm -> normalized e4m3 X
// ---------------------------------------------------------------------------
__global__ void ln_norm_kernel(const float* __restrict__ hs,
                               const float* __restrict__ gamma,
                               const float* __restrict__ beta)
{
    const int row = blockIdx.x;
    const int tid = threadIdx.x;                      // 256
    float4 v = ((const float4*)(hs + (size_t)row * H_))[tid];
    float s  = v.x + v.y + v.z + v.w;
    float ss = v.x*v.x + v.y*v.y + v.z*v.z + v.w*v.w;
    #pragma unroll
    for (int off = 16; off; off >>= 1) {
        s  += __shfl_down_sync(0xffffffffu, s,  off);
        ss += __shfl_down_sync(0xffffffffu, ss, off);
    }
    __shared__ float rs_[8], rss_[8];
    __shared__ float s_mu, s_rs;
    if ((tid & 31) == 0) { rs_[tid >> 5] = s; rss_[tid >> 5] = ss; }
    __syncthreads();
    if (tid == 0) {
        float S = 0.f, SS = 0.f;
        #pragma unroll
        for (int i = 0; i < 8; i++) { S += rs_[i]; SS += rss_[i]; }
        float mu  = S * (1.0f / H_);
        float var = SS * (1.0f / H_) - mu * mu;
        s_mu = mu; s_rs = rsqrtf(var + EPS_);
    }
    __syncthreads();
    const float mu = s_mu, rstd = s_rs;
    float4 g4 = ((const float4*)gamma)[tid];
    float4 b4 = ((const float4*)beta)[tid];
    float o0 = (v.x - mu) * rstd * g4.x + b4.x;
    float o1 = (v.y - mu) * rstd * g4.y + b4.y;
    float o2 = (v.z - mu) * rstd * g4.z + b4.z;
    float o3 = (v.w - mu) * rstd * g4.w + b4.w;
    uint32_t lo = f2e4m3x2_(o1, o0);
    uint32_t hi = f2e4m3x2_(o3, o2);
    *(uint32_t*)(g_x8 + (size_t)row * H_ + tid * 4) = lo | (hi << 16);
}

// ---------------------------------------------------------------------------
// Kernel 2: W1 [K=1024][N=512] fp32 -> (W1*64)^T e4m3 [N][K]
// ---------------------------------------------------------------------------
__global__ void w1_transpose_kernel(const float* __restrict__ W1)
{
    __shared__ float tile[32][33];
    const int n0 = blockIdx.x * 32, k0 = blockIdx.y * 32;
    const int tx = threadIdx.x, ty = threadIdx.y;   // (32, 8)
    #pragma unroll
    for (int i = 0; i < 4; i++)
        tile[ty + 8*i][tx] = W1[(size_t)(k0 + ty + 8*i) * HD2 + n0 + tx];
    __syncthreads();
    #pragma unroll
    for (int i = 0; i < 4; i++) {
        uint16_t p = f2e4m3x2_(0.f, tile[tx][ty + 8*i] * W1SCL);
        g_w1t8[(size_t)(n0 + ty + 8*i) * H_ + k0 + tx] = (uint8_t)(p & 0xff);
    }
}

// ---------------------------------------------------------------------------
// Kernel 3: GEMM1 e4m3 mma.sync m16n8k32, f16 accumulate.
// CTA tile 128(M)x128(N), 256 threads (8 warps 2Mx4N), warp tile 64x32,
// K-tile = 64 bytes, 3-stage cp.async, ldmatrix.x4, 3 CTAs/SM.
// ---------------------------------------------------------------------------
#define ROWB    80                       // 64B data + 16B pad
#define TILE_A  (128 * ROWB)             // 10240
#define TILE_BB (128 * ROWB)             // 10240
#define STG_B   (TILE_A + TILE_BB)       // 20480
#define NSTG    3
#define NKT     16                       // 1024B / 64B
#define GEMM1_SMEM (NSTG * STG_B)        // 61440

__global__ void __launch_bounds__(256, 3) gemm1_tc_kernel(const float* __restrict__ b1)
{
    extern __shared__ __align__(16) char dsm[];
    const uint32_t sbase = (uint32_t)__cvta_generic_to_shared(dsm);

    const int tid  = threadIdx.x;
    const int m0   = blockIdx.y * 128;
    const int n0   = blockIdx.x * 128;
    const int warp = tid >> 5, lane = tid & 31;
    const int wm   = warp & 1;            // M half (64 rows)
    const int wn   = warp >> 1;           // N quarter (32 cols)

    uint32_t offA[4], offB[2];
    {
        const int rA = (lane & 15);
        const int cA = (lane >> 4);
        #pragma unroll
        for (int mt = 0; mt < 4; mt++)
            offA[mt] = (uint32_t)((wm * 64 + mt * 16 + rA) * ROWB + cA * 16);
        const int rB = (lane & 7) + ((lane >> 4) << 3);
        const int cB = (lane >> 3) & 1;
        #pragma unroll
        for (int p = 0; p < 2; p++)
            offB[p] = (uint32_t)(TILE_A + (wn * 32 + p * 16 + rB) * ROWB + cB * 16);
    }

    // loaders: 1 thread per row; tid<128 -> A row, tid>=128 -> B row. 4x16B each.
    const int lrow = tid & 127;
    const int isB  = tid >> 7;
    const uint8_t* Sg = isB ? (g_w1t8 + (size_t)(n0 + lrow) * H_)
                            : (g_x8   + (size_t)(m0 + lrow) * H_);
    const uint32_t dS = sbase + isB * TILE_A + lrow * ROWB;

    uint32_t acc[4][4][2];                 // f16x2 accumulators
    #pragma unroll
    for (int mt = 0; mt < 4; mt++)
        #pragma unroll
        for (int nt = 0; nt < 4; nt++) { acc[mt][nt][0] = 0u; acc[mt][nt][1] = 0u; }

    #pragma unroll
    for (int p = 0; p < 2; ++p) {
        const uint32_t sg = p * STG_B;
        #pragma unroll
        for (int c = 0; c < 4; c++)
            cp16s(dS + sg + c * 16, Sg + p * 64 + c * 16);
        asm volatile("cp.async.commit_group;");
    }

    for (int t = 0; t < NKT; ++t) {
        if (t < NKT - 1) asm volatile("cp.async.wait_group 1;");
        else             asm volatile("cp.async.wait_group 0;");
        __syncthreads();

        const uint32_t sS = sbase + (t % NSTG) * STG_B;
        #pragma unroll
        for (int kt = 0; kt < 2; ++kt) {            // two k32 steps per 64B row
            uint32_t a[4][4], b[2][4];
            #pragma unroll
            for (int mt = 0; mt < 4; mt++) ldsm4(a[mt], sS + offA[mt] + kt * 32);
            #pragma unroll
            for (int p = 0; p < 2; p++)    ldsm4(b[p],  sS + offB[p]  + kt * 32);
            #pragma unroll
            for (int mt = 0; mt < 4; mt++)
                #pragma unroll
                for (int nt = 0; nt < 4; nt++) {
                    const uint32_t b0  = b[nt >> 1][(nt & 1) * 2];
                    const uint32_t b1r = b[nt >> 1][(nt & 1) * 2 + 1];
                    asm volatile(
                        "mma.sync.aligned.m16n8k32.row.col.f16.e4m3.e4m3.f16 "
                        "{%0,%1},{%2,%3,%4,%5},{%6,%7},{%0,%1};"
                        : "+r"(acc[mt][nt][0]), "+r"(acc[mt][nt][1])
                        : "r"(a[mt][0]), "r"(a[mt][1]), "r"(a[mt][2]), "r"(a[mt][3]),
                          "r"(b0), "r"(b1r));
                }
        }

        if (t + 2 < NKT) {
            const uint32_t sg = ((t + 2) % NSTG) * STG_B;
            const int k0 = (t + 2) * 64;
            #pragma unroll
            for (int c = 0; c < 4; c++)
                cp16s(dS + sg + c * 16, Sg + k0 + c * 16);
            asm volatile("cp.async.commit_group;");
        }
    }

    // epilogue: /64, +b1, exact GELU, bf16 store
    const int r = lane >> 2, tig = lane & 3;
    #pragma unroll
    for (int nt = 0; nt < 4; nt++) {
        const int col = n0 + wn * 32 + nt * 8 + 2 * tig;
        const float bx = __ldg(b1 + col), by = __ldg(b1 + col + 1);
        #pragma unroll
        for (int mt = 0; mt < 4; mt++) {
            const int row = m0 + wm * 64 + mt * 16 + r;
            float2 f01 = __half22float2(*(__half2*)&acc[mt][nt][0]);
            float2 f23 = __half22float2(*(__half2*)&acc[mt][nt][1]);
            float c0 = f01.x * W1INV + bx, c1 = f01.y * W1INV + by;
            float c2 = f23.x * W1INV + bx, c3 = f23.y * W1INV + by;
            c0 = 0.5f * c0 * (1.0f + erff(c0 * 0.70710678118654752f));
            c1 = 0.5f * c1 * (1.0f + erff(c1 * 0.70710678118654752f));
            c2 = 0.5f * c2 * (1.0f + erff(c2 * 0.70710678118654752f));
            c3 = 0.5f * c3 * (1.0f + erff(c3 * 0.70710678118654752f));
            *(__nv_bfloat162*)(g_hb + (size_t)row * HD2 + col)       = __floats2bfloat162_rn(c0, c1);
            *(__nv_bfloat162*)(g_hb + (size_t)(row + 8) * HD2 + col) = __floats2bfloat162_rn(c2, c3);
        }
    }
}

// ---------------------------------------------------------------------------
// Kernel 4: GEMM2 split-K2, 64 tokens / 128-thread block, grid 512.
// ---------------------------------------------------------------------------
__global__ void __launch_bounds__(128) gemm2_kernel(
    const float* __restrict__ W2, const float* __restrict__ b2)
{
    __shared__ float w2s[HD2 * 12];   // 24 KB, row k -> 12 floats (9 used)
    __shared__ float b2s[L_];
    for (int i = threadIdx.x; i < HD2 * L_; i += 128)
        w2s[(i / L_) * 12 + (i % L_)] = W2[i];
    if (threadIdx.x < L_) b2s[threadIdx.x] = b2[threadIdx.x];
    __syncthreads();

    const int warp = threadIdx.x >> 5;
    const int lane = threadIdx.x & 31;
    const int half = lane >> 4;
    const int tok  = blockIdx.x * 64 + warp * 16 + (lane & 15);

    const uint4* hp = (const uint4*)(g_hb + (size_t)tok * HD2 + half * 256);
    const float* wbase = &w2s[(half * 256) * 12];

    float acc[L_];
    #pragma unroll
    for (int l = 0; l < L_; l++) acc[l] = 0.f;

    #pragma unroll 8
    for (int c = 0; c < 32; ++c) {
        uint4 v = hp[c];
        float h[8];
        h[0] = __uint_as_float(v.x << 16); h[1] = __uint_as_float(v.x & 0xffff0000u);
        h[2] = __uint_as_float(v.y << 16); h[3] = __uint_as_float(v.y & 0xffff0000u);
        h[4] = __uint_as_float(v.z << 16); h[5] = __uint_as_float(v.z & 0xffff0000u);
        h[6] = __uint_as_float(v.w << 16); h[7] = __uint_as_float(v.w & 0xffff0000u);
        #pragma unroll
        for (int j = 0; j < 8; j++) {
            const float* w = wbase + (c * 8 + j) * 12;
            float4 w0 = *(const float4*)(w);
            float4 w1 = *(const float4*)(w + 4);
            float  w8 = w[8];
            acc[0] = fmaf(h[j], w0.x, acc[0]);
            acc[1] = fmaf(h[j], w0.y, acc[1]);
            acc[2] = fmaf(h[j], w0.z, acc[2]);
            acc[3] = fmaf(h[j], w0.w, acc[3]);
            acc[4] = fmaf(h[j], w1.x, acc[4]);
            acc[5] = fmaf(h[j], w1.y, acc[5]);
            acc[6] = fmaf(h[j], w1.z, acc[6]);
            acc[7] = fmaf(h[j], w1.w, acc[7]);
            acc[8] = fmaf(h[j], w8,   acc[8]);
        }
    }
    #pragma unroll
    for (int l = 0; l < L_; l++)
        acc[l] += __shfl_down_sync(0xffffffffu, acc[l], 16);
    if (half == 0) {
        float* out = g_em + (size_t)tok * L_;
        #pragma unroll
        for (int l = 0; l < L_; l++) out[l] = acc[l] + b2s[l];
    }
}

// ---------------------------------------------------------------------------
// Kernel 5: CRF. Ballot masks; linear-space scan; deep em prefetch.
// ---------------------------------------------------------------------------
__global__ void crf_kernel(const float* __restrict__ st,
                           const float* __restrict__ et,
                           const float* __restrict__ trans,
                           const int*   __restrict__ labels,
                           const int*   __restrict__ am)
{
    const int b    = blockIdx.x;
    const int lane = threadIdx.x;
    const float* em  = g_em + (size_t)b * S_ * L_;
    const int*   lab = labels + (size_t)b * S_;
    const int*   amk = am     + (size_t)b * S_;

    uint32_t mword[16];
    #pragma unroll
    for (int c = 0; c < 16; c++) {
        int t = c * 32 + lane;
        int l = lab[t];
        bool mk = (l != -100) && (amk[t] == 1);
        mword[c] = __ballot_sync(0xffffffffu, mk);
    }

    float part = 0.f;
    int   cnt  = 0;
    for (int t = lane; t < S_; t += 32) {
        bool rw = (mword[t >> 5] >> (t & 31)) & 1;
        bool mk = (t == 0) ? true : rw;
        if (mk) cnt++;
        if (t > 0 && rw) {
            int tp = lab[t - 1]; if (tp == -100) tp = 0;
            int tc = lab[t];     if (tc == -100) tc = 0;
            part += trans[tp * L_ + tc] + em[t * L_ + tc];
        }
    }
    #pragma unroll
    for (int off = 16; off; off >>= 1) {
        part += __shfl_down_sync(0xffffffffu, part, off);
        cnt  += __shfl_down_sync(0xffffffffu, cnt,  off);
    }
    float num = 0.f;
    if (lane == 0) {
        int tg0 = lab[0]; if (tg0 == -100) tg0 = 0;
        num = part + st[tg0] + em[tg0];
        int se = cnt - 1;
        int lt = lab[se]; if (lt == -100) lt = 0;
        num += et[lt];
    }

    const int j = lane;
    float c_[L_];
    #pragma unroll
    for (int i = 0; i < L_; i++)
        c_[i] = (j < L_) ? ex2f_(trans[i * L_ + j] * LOG2E_) : 0.f;

    float p  = (j < L_) ? ex2f_((st[j] + em[j]) * LOG2E_) : 0.f;
    float C2 = 0.f;

    float cur[8], nxt[8];
    #pragma unroll
    for (int i = 0; i < 8; i++)
        cur[i] = (j < L_) ? em[(1 + i) * L_ + j] : 0.f;

    for (int tb = 1; tb < S_; tb += 8) {
        #pragma unroll
        for (int i = 0; i < 8; i++) {
            int tn = tb + 8 + i;
            nxt[i] = (tn < S_ && j < L_) ? em[tn * L_ + j] : 0.f;
        }
        {
            float m = __shfl_sync(0xffffffffu, p, 0);
            int e = (__float_as_int(m) >> 23) & 255;
            float sc = __int_as_float((254 - e) << 23);
            p *= sc;
            C2 += (float)(e - 127);
        }
        #pragma unroll
        for (int i = 0; i < 8; i++) {
            int t = tb + i;
            if (t < S_) {
                float eem = ex2f_(cur[i] * LOG2E_);
                float pa[L_];
                #pragma unroll
                for (int q = 0; q < L_; q++) pa[q] = __shfl_sync(0xffffffffu, p, q);
                float s01 = fmaf(pa[1], c_[1], pa[0] * c_[0]);
                float s23 = fmaf(pa[3], c_[3], pa[2] * c_[2]);
                float s45 = fmaf(pa[5], c_[5], pa[4] * c_[4]);
                float s67 = fmaf(pa[7], c_[7], pa[6] * c_[6]);
                float s8  = pa[8] * c_[8];
                float s   = (s01 + s23) + (s45 + s67) + s8;
                float pn  = s * eem;
                bool mk = (mword[t >> 5] >> (t & 31)) & 1;
                p = mk ? pn : p;
            }
        }
        #pragma unroll
        for (int i = 0; i < 8; i++) cur[i] = nxt[i];
    }

    float fv = (j < L_) ? p * ex2f_(et[j] * LOG2E_) : 0.f;
    #pragma unroll
    for (int off = 16; off; off >>= 1) fv += __shfl_xor_sync(0xffffffffu, fv, off);
    float denom = (C2 + lg2f_(fv)) * LN2_;

    if (lane == 0) g_llh[b] = num - denom;
}

// ---------------------------------------------------------------------------
__global__ void finalize_kernel(float* __restrict__ out) {
    int t = threadIdx.x;                     // 64
    float v = g_llh[t];
    #pragma unroll
    for (int off = 16; off; off >>= 1) v += __shfl_down_sync(0xffffffffu, v, off);
    __shared__ float r[2];
    if ((t & 31) == 0) r[t >> 5] = v;
    __syncthreads();
    if (t == 0) out[0] = -((r[0] + r[1]) * (1.0f / B_));
}

// ---------------------------------------------------------------------------
extern "C" void kernel_launch(void* const* d_in, const int* in_sizes, int n_in,
                              void* d_out, int out_size)
{
    const float* hs    = (const float*)d_in[0];
    const float* gamma = (const float*)d_in[1];
    const float* beta  = (const float*)d_in[2];
    const float* W1    = (const float*)d_in[3];
    const float* b1    = (const float*)d_in[4];
    const float* W2    = (const float*)d_in[5];
    const float* b2    = (const float*)d_in[6];
    const float* st    = (const float*)d_in[7];
    const float* et    = (const float*)d_in[8];
    const float* trans = (const float*)d_in[9];
    const int*   labels= (const int*)d_in[10];
    const int*   am    = (const int*)d_in[11];

    cudaFuncSetAttribute(gemm1_tc_kernel,
                         cudaFuncAttributeMaxDynamicSharedMemorySize, GEMM1_SMEM);

    ln_norm_kernel<<<NTOK, 256>>>(hs, gamma, beta);
    w1_transpose_kernel<<<dim3(HD2 / 32, H_ / 32), dim3(32, 8)>>>(W1);
    marker_kernel<<<1, 32>>>();
    gemm1_tc_kernel<<<dim3(HD2 / 128, NTOK / 128), 256, GEMM1_SMEM>>>(b1);
    gemm2_kernel<<<NTOK / 64, 128>>>(W2, b2);
    crf_kernel<<<B_, 32>>>(st, et, trans, labels, am);
    finalize_kernel<<<1, 64>>>((float*)d_out);
}

// round 11
// speedup vs baseline: 1.4082x; 1.0464x over previous
#include <cuda_runtime.h>
#include <cuda_bf16.h>
#include <cuda_fp16.h>
#include <cuda_fp8.h>
#include <math.h>
#include <stdint.h>

#define B_    64
#define S_    512
#define H_    1024
#define HD2   512
#define L_    9
#define NTOK  (B_*S_)
#define EPS_  1e-5f
#define LOG2E_ 1.4426950408889634f
#define LN2_   0.6931471805599453f
#define W1SCL  64.0f
#define W1INV  0.015625f

// ---------------- device scratch (no allocation allowed) -------------------
__device__ uint8_t g_x8[(size_t)NTOK * H_];          // LN-normalized X, e4m3
__device__ uint8_t g_w1t8[(size_t)HD2 * H_];         // (W1*64)^T e4m3 [N][K]
__device__ float g_emp[4][(size_t)NTOK * L_];        // partial emissions per n-slice
__device__ float g_em[(size_t)NTOK * L_];            // emissions fp32
__device__ float g_llh[B_];

// ---------------------------------------------------------------------------
__device__ __forceinline__ float ex2f_(float x){ float y; asm("ex2.approx.ftz.f32 %0,%1;":"=f"(y):"f"(x)); return y; }
__device__ __forceinline__ float lg2f_(float x){ float y; asm("lg2.approx.ftz.f32 %0,%1;":"=f"(y):"f"(x)); return y; }

__device__ __forceinline__ void cp16s(uint32_t dst, const void* src){
    asm volatile("cp.async.cg.shared.global [%0], [%1], 16;" :: "r"(dst), "l"(src));
}
__device__ __forceinline__ void ldsm4(uint32_t* r, uint32_t addr){
    asm volatile("ldmatrix.sync.aligned.m8n8.x4.shared.b16 {%0,%1,%2,%3}, [%4];"
        : "=r"(r[0]), "=r"(r[1]), "=r"(r[2]), "=r"(r[3]) : "r"(addr));
}
__device__ __forceinline__ uint16_t f2e4m3x2_(float hi, float lo){
    uint16_t r;
    asm("cvt.rn.satfinite.e4m3x2.f32 %0, %1, %2;" : "=h"(r) : "f"(hi), "f"(lo));
    return r;
}
__device__ __forceinline__ float gelu_(float c){
    return 0.5f * c * (1.0f + erff(c * 0.70710678118654752f));
}

// ---------------------------------------------------------------------------
// no-op marker: keeps the launch sequence aligned so ncu captures gemm1
// ---------------------------------------------------------------------------
__global__ void marker_kernel() {}

// ---------------------------------------------------------------------------
// Kernel 1: LayerNorm -> normalized e4m3 X
// ---------------------------------------------------------------------------
__global__ void ln_norm_kernel(const float* __restrict__ hs,
                               const float* __restrict__ gamma,
                               const float* __restrict__ beta)
{
    const int row = blockIdx.x;
    const int tid = threadIdx.x;                      // 256
    float4 v = ((const float4*)(hs + (size_t)row * H_))[tid];
    float s  = v.x + v.y + v.z + v.w;
    float ss = v.x*v.x + v.y*v.y + v.z*v.z + v.w*v.w;
    #pragma unroll
    for (int off = 16; off; off >>= 1) {
        s  += __shfl_down_sync(0xffffffffu, s,  off);
        ss += __shfl_down_sync(0xffffffffu, ss, off);
    }
    __shared__ float rs_[8], rss_[8];
    __shared__ float s_mu, s_rs;
    if ((tid & 31) == 0) { rs_[tid >> 5] = s; rss_[tid >> 5] = ss; }
    __syncthreads();
    if (tid == 0) {
        float S = 0.f, SS = 0.f;
        #pragma unroll
        for (int i = 0; i < 8; i++) { S += rs_[i]; SS += rss_[i]; }
        float mu  = S * (1.0f / H_);
        float var = SS * (1.0f / H_) - mu * mu;
        s_mu = mu; s_rs = rsqrtf(var + EPS_);
    }
    __syncthreads();
    const float mu = s_mu, rstd = s_rs;
    float4 g4 = ((const float4*)gamma)[tid];
    float4 b4 = ((const float4*)beta)[tid];
    float o0 = (v.x - mu) * rstd * g4.x + b4.x;
    float o1 = (v.y - mu) * rstd * g4.y + b4.y;
    float o2 = (v.z - mu) * rstd * g4.z + b4.z;
    float o3 = (v.w - mu) * rstd * g4.w + b4.w;
    uint32_t lo = f2e4m3x2_(o1, o0);
    uint32_t hi = f2e4m3x2_(o3, o2);
    *(uint32_t*)(g_x8 + (size_t)row * H_ + tid * 4) = lo | (hi << 16);
}

// ---------------------------------------------------------------------------
// Kernel 2: W1 [K=1024][N=512] fp32 -> (W1*64)^T e4m3 [N][K]
// ---------------------------------------------------------------------------
__global__ void w1_transpose_kernel(const float* __restrict__ W1)
{
    __shared__ float tile[32][33];
    const int n0 = blockIdx.x * 32, k0 = blockIdx.y * 32;
    const int tx = threadIdx.x, ty = threadIdx.y;   // (32, 8)
    #pragma unroll
    for (int i = 0; i < 4; i++)
        tile[ty + 8*i][tx] = W1[(size_t)(k0 + ty + 8*i) * HD2 + n0 + tx];
    __syncthreads();
    #pragma unroll
    for (int i = 0; i < 4; i++) {
        uint16_t p = f2e4m3x2_(0.f, tile[tx][ty + 8*i] * W1SCL);
        g_w1t8[(size_t)(n0 + ty + 8*i) * H_ + k0 + tx] = (uint8_t)(p & 0xff);
    }
}

// ---------------------------------------------------------------------------
// Kernel 3: FUSED GEMM1+GELU+GEMM2-partial.
// e4m3 mma.sync m16n8k32, f16 acc; CTA tile 128(M)x128(N h-cols),
// 256 thr (8 warps 2Mx4N), warp tile 64x32, 3-stage cp.async.
// Epilogue: GELU then dot vs W2 slice (smem), staged reduction over the
// 4 N-warps, write partial emissions g_emp[n_slice].
// ---------------------------------------------------------------------------
#define ROWB    80                       // 64B data + 16B pad
#define TILE_A  (128 * ROWB)             // 10240
#define TILE_BB (128 * ROWB)             // 10240
#define STG_B   (TILE_A + TILE_BB)       // 20480
#define NSTG    3
#define NKT     16                       // 1024B / 64B
#define PIPE_B  (NSTG * STG_B)           // 61440
#define W2_OFF  PIPE_B                   // [128][12] floats = 6144 B
#define B1_OFF  (W2_OFF + 6144)          // 128 floats = 512 B
#define STGRED  (B1_OFF + 512)           // [4][32][12] floats = 6144 B
#define GEMM1_SMEM (STGRED + 6144)       // 74240

__global__ void __launch_bounds__(256, 3) gemm1_tc_kernel(
    const float* __restrict__ b1, const float* __restrict__ W2)
{
    extern __shared__ __align__(16) char dsm[];
    const uint32_t sbase = (uint32_t)__cvta_generic_to_shared(dsm);
    float* w2s = (float*)(dsm + W2_OFF);     // [128][12]
    float* b1s = (float*)(dsm + B1_OFF);     // [128]
    float* stg = (float*)(dsm + STGRED);     // [4][32][12]

    const int tid  = threadIdx.x;
    const int m0   = blockIdx.y * 128;
    const int n0   = blockIdx.x * 128;       // h-col slice base
    const int warp = tid >> 5, lane = tid & 31;
    const int wm   = warp & 1;               // M half (64 rows)
    const int wn   = warp >> 1;              // N quarter (32 cols)

    // preload W2 slice + b1 slice
    for (int i = tid; i < 128 * L_; i += 256)
        w2s[(i / L_) * 12 + (i % L_)] = W2[(size_t)(n0 + i / L_) * L_ + (i % L_)];
    if (tid < 128) b1s[tid] = b1[n0 + tid];

    uint32_t offA[4], offB[2];
    {
        const int rA = (lane & 15);
        const int cA = (lane >> 4);
        #pragma unroll
        for (int mt = 0; mt < 4; mt++)
            offA[mt] = (uint32_t)((wm * 64 + mt * 16 + rA) * ROWB + cA * 16);
        const int rB = (lane & 7) + ((lane >> 4) << 3);
        const int cB = (lane >> 3) & 1;
        #pragma unroll
        for (int p = 0; p < 2; p++)
            offB[p] = (uint32_t)(TILE_A + (wn * 32 + p * 16 + rB) * ROWB + cB * 16);
    }

    // loaders: 1 thread per row; tid<128 -> A row, tid>=128 -> B row. 4x16B.
    const int lrow = tid & 127;
    const int isB  = tid >> 7;
    const uint8_t* Sg = isB ? (g_w1t8 + (size_t)(n0 + lrow) * H_)
                            : (g_x8   + (size_t)(m0 + lrow) * H_);
    const uint32_t dS = sbase + isB * TILE_A + lrow * ROWB;

    uint32_t acc[4][4][2];                 // f16x2 accumulators
    #pragma unroll
    for (int mt = 0; mt < 4; mt++)
        #pragma unroll
        for (int nt = 0; nt < 4; nt++) { acc[mt][nt][0] = 0u; acc[mt][nt][1] = 0u; }

    #pragma unroll
    for (int p = 0; p < 2; ++p) {
        const uint32_t sg = p * STG_B;
        #pragma unroll
        for (int c = 0; c < 4; c++)
            cp16s(dS + sg + c * 16, Sg + p * 64 + c * 16);
        asm volatile("cp.async.commit_group;");
    }

    for (int t = 0; t < NKT; ++t) {
        if (t < NKT - 1) asm volatile("cp.async.wait_group 1;");
        else             asm volatile("cp.async.wait_group 0;");
        __syncthreads();

        const uint32_t sS = sbase + (t % NSTG) * STG_B;
        #pragma unroll
        for (int kt = 0; kt < 2; ++kt) {            // two k32 steps per 64B row
            uint32_t a[4][4], b[2][4];
            #pragma unroll
            for (int mt = 0; mt < 4; mt++) ldsm4(a[mt], sS + offA[mt] + kt * 32);
            #pragma unroll
            for (int p = 0; p < 2; p++)    ldsm4(b[p],  sS + offB[p]  + kt * 32);
            #pragma unroll
            for (int mt = 0; mt < 4; mt++)
                #pragma unroll
                for (int nt = 0; nt < 4; nt++) {
                    const uint32_t b0  = b[nt >> 1][(nt & 1) * 2];
                    const uint32_t b1r = b[nt >> 1][(nt & 1) * 2 + 1];
                    asm volatile(
                        "mma.sync.aligned.m16n8k32.row.col.f16.e4m3.e4m3.f16 "
                        "{%0,%1},{%2,%3,%4,%5},{%6,%7},{%0,%1};"
                        : "+r"(acc[mt][nt][0]), "+r"(acc[mt][nt][1])
                        : "r"(a[mt][0]), "r"(a[mt][1]), "r"(a[mt][2]), "r"(a[mt][3]),
                          "r"(b0), "r"(b1r));
                }
        }

        if (t + 2 < NKT) {
            const uint32_t sg = ((t + 2) % NSTG) * STG_B;
            const int k0 = (t + 2) * 64;
            #pragma unroll
            for (int c = 0; c < 4; c++)
                cp16s(dS + sg + c * 16, Sg + k0 + c * 16);
            asm volatile("cp.async.commit_group;");
        }
    }

    // ---- fused epilogue: GELU + dot with W2 slice + staged reduction ----
    const int r = lane >> 2, tig = lane & 3;
    #pragma unroll
    for (int mt = 0; mt < 4; mt++) {
        float e0[L_], e1[L_];
        #pragma unroll
        for (int l = 0; l < L_; l++) { e0[l] = 0.f; e1[l] = 0.f; }

        #pragma unroll
        for (int nt = 0; nt < 4; nt++) {
            const int c0 = wn * 32 + nt * 8 + 2 * tig;   // local h-col
            const float bx = b1s[c0], by = b1s[c0 + 1];
            float2 f01 = __half22float2(*(__half2*)&acc[mt][nt][0]);
            float2 f23 = __half22float2(*(__half2*)&acc[mt][nt][1]);
            float g00 = gelu_(f01.x * W1INV + bx);
            float g01 = gelu_(f01.y * W1INV + by);
            float g10 = gelu_(f23.x * W1INV + bx);
            float g11 = gelu_(f23.y * W1INV + by);
            const float* w0 = &w2s[c0 * 12];
            const float* w1 = &w2s[(c0 + 1) * 12];
            #pragma unroll
            for (int l = 0; l < L_; l++) {
                e0[l] = fmaf(g00, w0[l], fmaf(g01, w1[l], e0[l]));
                e1[l] = fmaf(g10, w0[l], fmaf(g11, w1[l], e1[l]));
            }
        }
        // reduce over the 4 tig lanes (cols within warp tile)
        #pragma unroll
        for (int l = 0; l < L_; l++) {
            e0[l] += __shfl_xor_sync(0xffffffffu, e0[l], 1);
            e0[l] += __shfl_xor_sync(0xffffffffu, e0[l], 2);
            e1[l] += __shfl_xor_sync(0xffffffffu, e1[l], 1);
            e1[l] += __shfl_xor_sync(0xffffffffu, e1[l], 2);
        }
        if (tig == 0) {
            float* s0 = &stg[(wn * 32 + wm * 16 + r) * 12];
            float* s1 = &stg[(wn * 32 + wm * 16 + r + 8) * 12];
            #pragma unroll
            for (int l = 0; l < L_; l++) { s0[l] = e0[l]; s1[l] = e1[l]; }
        }
        __syncthreads();
        // sum the 4 wn slices, write partial emissions
        for (int idx = tid; idx < 32 * L_; idx += 256) {
            const int wr = idx / L_, l = idx % L_;
            const int wmm = wr >> 4, rr = wr & 15;
            float v = stg[(0 * 32 + wr) * 12 + l] + stg[(1 * 32 + wr) * 12 + l]
                    + stg[(2 * 32 + wr) * 12 + l] + stg[(3 * 32 + wr) * 12 + l];
            const int row = m0 + wmm * 64 + mt * 16 + rr;
            g_emp[blockIdx.x][(size_t)row * L_ + l] = v;
        }
        __syncthreads();
    }
}

// ---------------------------------------------------------------------------
// Kernel 4: sum the 4 partial-emission slices + b2
// ---------------------------------------------------------------------------
__global__ void em_sum_kernel(const float* __restrict__ b2)
{
    const int l   = threadIdx.x;                        // 0..8
    const int tok = blockIdx.x * 32 + threadIdx.y;      // 32 tokens/block
    const size_t i = (size_t)tok * L_ + l;
    g_em[i] = g_emp[0][i] + g_emp[1][i] + g_emp[2][i] + g_emp[3][i] + b2[l];
}

// ---------------------------------------------------------------------------
// Kernel 5: CRF. Ballot masks; linear-space scan; deep em prefetch.
// ---------------------------------------------------------------------------
__global__ void crf_kernel(const float* __restrict__ st,
                           const float* __restrict__ et,
                           const float* __restrict__ trans,
                           const int*   __restrict__ labels,
                           const int*   __restrict__ am)
{
    const int b    = blockIdx.x;
    const int lane = threadIdx.x;
    const float* em  = g_em + (size_t)b * S_ * L_;
    const int*   lab = labels + (size_t)b * S_;
    const int*   amk = am     + (size_t)b * S_;

    uint32_t mword[16];
    #pragma unroll
    for (int c = 0; c < 16; c++) {
        int t = c * 32 + lane;
        int l = lab[t];
        bool mk = (l != -100) && (amk[t] == 1);
        mword[c] = __ballot_sync(0xffffffffu, mk);
    }

    float part = 0.f;
    int   cnt  = 0;
    for (int t = lane; t < S_; t += 32) {
        bool rw = (mword[t >> 5] >> (t & 31)) & 1;
        bool mk = (t == 0) ? true : rw;
        if (mk) cnt++;
        if (t > 0 && rw) {
            int tp = lab[t - 1]; if (tp == -100) tp = 0;
            int tc = lab[t];     if (tc == -100) tc = 0;
            part += trans[tp * L_ + tc] + em[t * L_ + tc];
        }
    }
    #pragma unroll
    for (int off = 16; off; off >>= 1) {
        part += __shfl_down_sync(0xffffffffu, part, off);
        cnt  += __shfl_down_sync(0xffffffffu, cnt,  off);
    }
    float num = 0.f;
    if (lane == 0) {
        int tg0 = lab[0]; if (tg0 == -100) tg0 = 0;
        num = part + st[tg0] + em[tg0];
        int se = cnt - 1;
        int lt = lab[se]; if (lt == -100) lt = 0;
        num += et[lt];
    }

    const int j = lane;
    float c_[L_];
    #pragma unroll
    for (int i = 0; i < L_; i++)
        c_[i] = (j < L_) ? ex2f_(trans[i * L_ + j] * LOG2E_) : 0.f;

    float p  = (j < L_) ? ex2f_((st[j] + em[j]) * LOG2E_) : 0.f;
    float C2 = 0.f;

    float cur[8], nxt[8];
    #pragma unroll
    for (int i = 0; i < 8; i++)
        cur[i] = (j < L_) ? em[(1 + i) * L_ + j] : 0.f;

    for (int tb = 1; tb < S_; tb += 8) {
        #pragma unroll
        for (int i = 0; i < 8; i++) {
            int tn = tb + 8 + i;
            nxt[i] = (tn < S_ && j < L_) ? em[tn * L_ + j] : 0.f;
        }
        {
            float m = __shfl_sync(0xffffffffu, p, 0);
            int e = (__float_as_int(m) >> 23) & 255;
            float sc = __int_as_float((254 - e) << 23);
            p *= sc;
            C2 += (float)(e - 127);
        }
        #pragma unroll
        for (int i = 0; i < 8; i++) {
            int t = tb + i;
            if (t < S_) {
                float eem = ex2f_(cur[i] * LOG2E_);
                float pa[L_];
                #pragma unroll
                for (int q = 0; q < L_; q++) pa[q] = __shfl_sync(0xffffffffu, p, q);
                float s01 = fmaf(pa[1], c_[1], pa[0] * c_[0]);
                float s23 = fmaf(pa[3], c_[3], pa[2] * c_[2]);
                float s45 = fmaf(pa[5], c_[5], pa[4] * c_[4]);
                float s67 = fmaf(pa[7], c_[7], pa[6] * c_[6]);
                float s8  = pa[8] * c_[8];
                float s   = (s01 + s23) + (s45 + s67) + s8;
                float pn  = s * eem;
                bool mk = (mword[t >> 5] >> (t & 31)) & 1;
                p = mk ? pn : p;
            }
        }
        #pragma unroll
        for (int i = 0; i < 8; i++) cur[i] = nxt[i];
    }

    float fv = (j < L_) ? p * ex2f_(et[j] * LOG2E_) : 0.f;
    #pragma unroll
    for (int off = 16; off; off >>= 1) fv += __shfl_xor_sync(0xffffffffu, fv, off);
    float denom = (C2 + lg2f_(fv)) * LN2_;

    if (lane == 0) g_llh[b] = num - denom;
}

// ---------------------------------------------------------------------------
__global__ void finalize_kernel(float* __restrict__ out) {
    int t = threadIdx.x;                     // 64
    float v = g_llh[t];
    #pragma unroll
    for (int off = 16; off; off >>= 1) v += __shfl_down_sync(0xffffffffu, v, off);
    __shared__ float r[2];
    if ((t & 31) == 0) r[t >> 5] = v;
    __syncthreads();
    if (t == 0) out[0] = -((r[0] + r[1]) * (1.0f / B_));
}

// ---------------------------------------------------------------------------
extern "C" void kernel_launch(void* const* d_in, const int* in_sizes, int n_in,
                              void* d_out, int out_size)
{
    const float* hs    = (const float*)d_in[0];
    const float* gamma = (const float*)d_in[1];
    const float* beta  = (const float*)d_in[2];
    const float* W1    = (const float*)d_in[3];
    const float* b1    = (const float*)d_in[4];
    const float* W2    = (const float*)d_in[5];
    const float* b2    = (const float*)d_in[6];
    const float* st    = (const float*)d_in[7];
    const float* et    = (const float*)d_in[8];
    const float* trans = (const float*)d_in[9];
    const int*   labels= (const int*)d_in[10];
    const int*   am    = (const int*)d_in[11];

    cudaFuncSetAttribute(gemm1_tc_kernel,
                         cudaFuncAttributeMaxDynamicSharedMemorySize, GEMM1_SMEM);

    ln_norm_kernel<<<NTOK, 256>>>(hs, gamma, beta);
    w1_transpose_kernel<<<dim3(HD2 / 32, H_ / 32), dim3(32, 8)>>>(W1);
    marker_kernel<<<1, 32>>>();
    gemm1_tc_kernel<<<dim3(HD2 / 128, NTOK / 128), 256, GEMM1_SMEM>>>(b1, W2);
    em_sum_kernel<<<NTOK / 32, dim3(L_, 32)>>>(b2);
    crf_kernel<<<B_, 32>>>(st, et, trans, labels, am);
    finalize_kernel<<<1, 64>>>((float*)d_out);
}